// round 1
// baseline (speedup 1.0000x reference)
#include <cuda_runtime.h>
#include <cstdint>

// Problem constants
#define BB    8
#define CC    256
#define HH    96
#define WW    96
#define HEADS 8
#define HD    32
#define KW    7
#define HW_   (HH * WW)          // 9216
#define NPIX  (BB * HW_)         // 73728

// Attention tiling
#define TI   16
#define TJ   16
#define ER   22                  // TI + KW - 1 halo rows/cols
#define PSTR 36                  // padded per-pixel stride in floats (bank-spread)

// Scratch: q,k,v,attn-out in (B, HW, C) layout (head vector contiguous)
__device__ float g_q[(size_t)NPIX * CC];
__device__ float g_k[(size_t)NPIX * CC];
__device__ float g_v[(size_t)NPIX * CC];
__device__ float g_o[(size_t)NPIX * CC];

// ---------------------------------------------------------------------------
// Fused QKV GEMM: q/k/v[(b*HW+hw)*C + o] = sum_c w*[o,c] * x[b,c,hw]
// Tile: 64 pixels x 64 out-channels x 16 k-step. 256 threads, 4x4x3 regs.
// ---------------------------------------------------------------------------
__global__ __launch_bounds__(256) void qkv_kernel(
    const float* __restrict__ x,
    const float* __restrict__ wq,
    const float* __restrict__ wk,
    const float* __restrict__ wv)
{
    __shared__ float xs[16][64];
    __shared__ float wsq[16][64];
    __shared__ float wsk[16][64];
    __shared__ float wsv[16][64];

    const int mt  = blockIdx.x;            // 0..1151, never crosses batch (144/b)
    const int b   = mt / (HW_ / 64);
    const int hw0 = (mt % (HW_ / 64)) * 64;
    const int n0  = blockIdx.y * 64;
    const int tid = threadIdx.x;
    const int ty  = tid >> 4;              // 0..15 : pixel group
    const int tx  = tid & 15;              // 0..15 : channel group

    const float* xb = x + (size_t)b * CC * HW_ + hw0;

    float aq[4][4] = {}, ak[4][4] = {}, av[4][4] = {};

    const int lr = tid >> 4;               // xs load row (c)
    const int lc = (tid & 15) * 4;         // xs load col (pixel)
    const int wo = tid >> 2;               // weight load: out-channel 0..63
    const int wc = (tid & 3) * 4;          // weight load: c offset

    for (int k0 = 0; k0 < CC; k0 += 16) {
        float4 xv = *(const float4*)(xb + (size_t)(k0 + lr) * HW_ + lc);
        *(float4*)&xs[lr][lc] = xv;

        float4 t;
        t = *(const float4*)(wq + (size_t)(n0 + wo) * CC + k0 + wc);
        wsq[wc + 0][wo] = t.x; wsq[wc + 1][wo] = t.y;
        wsq[wc + 2][wo] = t.z; wsq[wc + 3][wo] = t.w;
        t = *(const float4*)(wk + (size_t)(n0 + wo) * CC + k0 + wc);
        wsk[wc + 0][wo] = t.x; wsk[wc + 1][wo] = t.y;
        wsk[wc + 2][wo] = t.z; wsk[wc + 3][wo] = t.w;
        t = *(const float4*)(wv + (size_t)(n0 + wo) * CC + k0 + wc);
        wsv[wc + 0][wo] = t.x; wsv[wc + 1][wo] = t.y;
        wsv[wc + 2][wo] = t.z; wsv[wc + 3][wo] = t.w;
        __syncthreads();

        #pragma unroll
        for (int kk = 0; kk < 16; kk++) {
            float4 a  = *(const float4*)&xs[kk][ty * 4];
            float4 bq = *(const float4*)&wsq[kk][tx * 4];
            float4 bk = *(const float4*)&wsk[kk][tx * 4];
            float4 bv = *(const float4*)&wsv[kk][tx * 4];
            const float ar[4] = {a.x, a.y, a.z, a.w};
            const float bqr[4] = {bq.x, bq.y, bq.z, bq.w};
            const float bkr[4] = {bk.x, bk.y, bk.z, bk.w};
            const float bvr[4] = {bv.x, bv.y, bv.z, bv.w};
            #pragma unroll
            for (int pi = 0; pi < 4; pi++)
                #pragma unroll
                for (int oi = 0; oi < 4; oi++) {
                    aq[pi][oi] += ar[pi] * bqr[oi];
                    ak[pi][oi] += ar[pi] * bkr[oi];
                    av[pi][oi] += ar[pi] * bvr[oi];
                }
        }
        __syncthreads();
    }

    const float scale = 0.17677669529663687f;  // 1/sqrt(32)
    float* qb = g_q + ((size_t)(b * HW_ + hw0)) * CC + n0;
    float* kb = g_k + ((size_t)(b * HW_ + hw0)) * CC + n0;
    float* vb = g_v + ((size_t)(b * HW_ + hw0)) * CC + n0;
    #pragma unroll
    for (int pi = 0; pi < 4; pi++) {
        const size_t po = (size_t)(ty * 4 + pi) * CC + tx * 4;
        float4 rq = {aq[pi][0] * scale, aq[pi][1] * scale,
                     aq[pi][2] * scale, aq[pi][3] * scale};
        float4 rk = {ak[pi][0], ak[pi][1], ak[pi][2], ak[pi][3]};
        float4 rv = {av[pi][0], av[pi][1], av[pi][2], av[pi][3]};
        *(float4*)(qb + po) = rq;
        *(float4*)(kb + po) = rk;
        *(float4*)(vb + po) = rv;
    }
}

// ---------------------------------------------------------------------------
// Neighborhood attention: one block per (b, head, 16x16 pixel tile).
// Stage 22x22 halo of k and v (+13x13 rpb) in smem; thread-per-pixel.
// ---------------------------------------------------------------------------
extern __shared__ float sm_attn[];

__global__ __launch_bounds__(256) void attn_kernel(const float* __restrict__ rpb)
{
    float* ks = sm_attn;
    float* vs = sm_attn + ER * ER * PSTR;
    float* rs = vs + ER * ER * PSTR;       // 169 floats

    const int tile = blockIdx.x;           // 0..35
    const int head = blockIdx.y;
    const int b    = blockIdx.z;
    const int i0   = (tile / (WW / TJ)) * TI;
    const int j0   = (tile % (WW / TJ)) * TJ;
    const int tid  = threadIdx.x;

    const int rb = min(max(i0 - 3, 0), HH - KW);   // halo row base
    const int cb = min(max(j0 - 3, 0), WW - KW);   // halo col base

    const float* kbase = g_k + (size_t)b * HW_ * CC + head * HD;
    const float* vbase = g_v + (size_t)b * HW_ * CC + head * HD;

    for (int t = tid; t < ER * ER * 8; t += 256) {
        const int pix = t >> 3, d4 = t & 7;
        const int rr = min(rb + pix / ER, HH - 1);
        const int cc = min(cb + pix % ER, WW - 1);
        const size_t go = (size_t)(rr * WW + cc) * CC + d4 * 4;
        *(float4*)&ks[pix * PSTR + d4 * 4] = *(const float4*)(kbase + go);
        *(float4*)&vs[pix * PSTR + d4 * 4] = *(const float4*)(vbase + go);
    }
    if (tid < 169) rs[tid] = rpb[head * 169 + tid];
    __syncthreads();

    const int ti = tid >> 4, tj = tid & 15;
    const int i = i0 + ti, j = j0 + tj;
    const int sh = min(max(i - 3, 0), HH - KW);
    const int sw = min(max(j - 3, 0), WW - KW);
    const int dbi = sh - i + 6, dbj = sw - j + 6;  // rpb row/col base
    const int prow = sh - rb, pcol = sw - cb;      // local halo base

    const float* qp = g_q + ((size_t)(b * HW_) + i * WW + j) * CC + head * HD;
    float4 q[8];
    #pragma unroll
    for (int d = 0; d < 8; d++) q[d] = *(const float4*)(qp + d * 4);

    float lg[49];
    float mx = -1e30f;
    #pragma unroll
    for (int ki = 0; ki < KW; ki++) {
        #pragma unroll
        for (int kj = 0; kj < KW; kj++) {
            const float* kp = &ks[((prow + ki) * ER + pcol + kj) * PSTR];
            float acc = 0.f;
            #pragma unroll
            for (int d = 0; d < 8; d++) {
                float4 kv = *(const float4*)(kp + d * 4);
                acc += q[d].x * kv.x + q[d].y * kv.y +
                       q[d].z * kv.z + q[d].w * kv.w;
            }
            acc += rs[(dbi + ki) * 13 + (dbj + kj)];
            lg[ki * KW + kj] = acc;
            mx = fmaxf(mx, acc);
        }
    }

    float s = 0.f;
    #pragma unroll
    for (int n = 0; n < 49; n++) {
        float e = __expf(lg[n] - mx);
        lg[n] = e;
        s += e;
    }
    const float inv = 1.0f / s;

    float4 o[8];
    #pragma unroll
    for (int d = 0; d < 8; d++) o[d] = make_float4(0.f, 0.f, 0.f, 0.f);

    #pragma unroll
    for (int ki = 0; ki < KW; ki++) {
        #pragma unroll
        for (int kj = 0; kj < KW; kj++) {
            const float w = lg[ki * KW + kj];
            const float* vp = &vs[((prow + ki) * ER + pcol + kj) * PSTR];
            #pragma unroll
            for (int d = 0; d < 8; d++) {
                float4 vv = *(const float4*)(vp + d * 4);
                o[d].x += w * vv.x; o[d].y += w * vv.y;
                o[d].z += w * vv.z; o[d].w += w * vv.w;
            }
        }
    }

    float* op = g_o + ((size_t)(b * HW_) + i * WW + j) * CC + head * HD;
    #pragma unroll
    for (int d = 0; d < 8; d++) {
        float4 r = {o[d].x * inv, o[d].y * inv, o[d].z * inv, o[d].w * inv};
        *(float4*)(op + d * 4) = r;
    }
}

// ---------------------------------------------------------------------------
// Output projection: y[b,o,hw] = sum_c wp[o,c]*m[(b*HW+hw)*C+c] + bp[o]
// ---------------------------------------------------------------------------
__global__ __launch_bounds__(256) void proj_kernel(
    const float* __restrict__ wp,
    const float* __restrict__ bp,
    float* __restrict__ y)
{
    __shared__ float ms[16][64];   // [c][pixel]
    __shared__ float ws[16][64];   // [c][o]

    const int mt  = blockIdx.x;
    const int b   = mt / (HW_ / 64);
    const int hw0 = (mt % (HW_ / 64)) * 64;
    const int n0  = blockIdx.y * 64;
    const int tid = threadIdx.x;
    const int ty  = tid >> 4, tx = tid & 15;

    const float* mb = g_o + ((size_t)(b * HW_ + hw0)) * CC;

    float acc[4][4] = {};  // [oi][pi]

    const int lp = tid >> 2;        // pixel / out-channel for loads (0..63)
    const int lc = (tid & 3) * 4;   // c offset

    for (int k0 = 0; k0 < CC; k0 += 16) {
        float4 mv = *(const float4*)(mb + (size_t)lp * CC + k0 + lc);
        ms[lc + 0][lp] = mv.x; ms[lc + 1][lp] = mv.y;
        ms[lc + 2][lp] = mv.z; ms[lc + 3][lp] = mv.w;
        float4 wv4 = *(const float4*)(wp + (size_t)(n0 + lp) * CC + k0 + lc);
        ws[lc + 0][lp] = wv4.x; ws[lc + 1][lp] = wv4.y;
        ws[lc + 2][lp] = wv4.z; ws[lc + 3][lp] = wv4.w;
        __syncthreads();

        #pragma unroll
        for (int kk = 0; kk < 16; kk++) {
            float4 a  = *(const float4*)&ms[kk][ty * 4];
            float4 w4 = *(const float4*)&ws[kk][tx * 4];
            const float ar[4] = {a.x, a.y, a.z, a.w};
            const float wr[4] = {w4.x, w4.y, w4.z, w4.w};
            #pragma unroll
            for (int oi = 0; oi < 4; oi++)
                #pragma unroll
                for (int pi = 0; pi < 4; pi++)
                    acc[oi][pi] += wr[oi] * ar[pi];
        }
        __syncthreads();
    }

    float* yb = y + (size_t)b * CC * HW_ + hw0;
    #pragma unroll
    for (int oi = 0; oi < 4; oi++) {
        const int o = n0 + tx * 4 + oi;
        const float bv = bp[o];
        float4 r = {acc[oi][0] + bv, acc[oi][1] + bv,
                    acc[oi][2] + bv, acc[oi][3] + bv};
        *(float4*)(yb + (size_t)o * HW_ + ty * 4) = r;
    }
}

// ---------------------------------------------------------------------------
extern "C" void kernel_launch(void* const* d_in, const int* in_sizes, int n_in,
                              void* d_out, int out_size)
{
    const float* x   = (const float*)d_in[0];
    const float* wq  = (const float*)d_in[1];
    const float* wk  = (const float*)d_in[2];
    const float* wv  = (const float*)d_in[3];
    const float* wp  = (const float*)d_in[4];
    const float* bp  = (const float*)d_in[5];
    const float* rpb = (const float*)d_in[6];
    float* y = (float*)d_out;

    // QKV projections
    qkv_kernel<<<dim3(NPIX / 64, CC / 64), 256>>>(x, wq, wk, wv);

    // Neighborhood attention
    const int smem_bytes = (2 * ER * ER * PSTR + 169) * (int)sizeof(float);
    (void)cudaFuncSetAttribute(attn_kernel,
                               cudaFuncAttributeMaxDynamicSharedMemorySize,
                               smem_bytes);
    attn_kernel<<<dim3((HH / TI) * (WW / TJ), HEADS, BB), 256, smem_bytes>>>(rpb);

    // Output projection + bias
    proj_kernel<<<dim3(NPIX / 64, CC / 64), 256>>>(wp, bp, y);
}

// round 3
// speedup vs baseline: 1.7329x; 1.7329x over previous
#include <cuda_runtime.h>
#include <cuda_bf16.h>
#include <cstdint>

// Problem constants
#define BB    8
#define CC    256
#define HH    96
#define WW    96
#define HEADS 8
#define HD    32
#define KW    7
#define HW_   (HH * WW)          // 9216
#define NPIX  (BB * HW_)         // 73728

// Attention tiling
#define TI   16
#define TJ   16
#define ER   22
#define PSTR 36

// Scratch
__device__ float g_q[(size_t)NPIX * CC];
__device__ float g_k[(size_t)NPIX * CC];
__device__ float g_v[(size_t)NPIX * CC];

// bf16 split operands
__device__ __nv_bfloat16 g_xh[(size_t)NPIX * CC];
__device__ __nv_bfloat16 g_xl[(size_t)NPIX * CC];
__device__ __nv_bfloat16 g_oh[(size_t)NPIX * CC];
__device__ __nv_bfloat16 g_ol[(size_t)NPIX * CC];
__device__ __nv_bfloat16 g_wh[4 * CC * CC];
__device__ __nv_bfloat16 g_wl[4 * CC * CC];

// ---------------------------------------------------------------------------
// Helpers
// ---------------------------------------------------------------------------
__device__ __forceinline__ uint32_t smem_u32(const void* p) {
    uint32_t a;
    asm("{ .reg .u64 t; cvta.to.shared.u64 t, %1; cvt.u32.u64 %0, t; }"
        : "=r"(a) : "l"(p));
    return a;
}

__device__ __forceinline__ void ldsm_x4(uint32_t* r, uint32_t addr) {
    asm volatile("ldmatrix.sync.aligned.m8n8.x4.shared.b16 {%0,%1,%2,%3}, [%4];"
        : "=r"(r[0]), "=r"(r[1]), "=r"(r[2]), "=r"(r[3]) : "r"(addr));
}

__device__ __forceinline__ void mma_bf16(float* d, const uint32_t* a,
                                         const uint32_t* b, const float* c) {
    asm volatile(
        "mma.sync.aligned.m16n8k16.row.col.f32.bf16.bf16.f32 "
        "{%0,%1,%2,%3}, {%4,%5,%6,%7}, {%8,%9}, {%10,%11,%12,%13};"
        : "=f"(d[0]), "=f"(d[1]), "=f"(d[2]), "=f"(d[3])
        : "r"(a[0]), "r"(a[1]), "r"(a[2]), "r"(a[3]),
          "r"(b[0]), "r"(b[1]),
          "f"(c[0]), "f"(c[1]), "f"(c[2]), "f"(c[3]));
}

#define SW128(o) ((o) ^ (((o) >> 3) & 0x70))

// smem layout for gemm kernels (static 48KB, 1024-aligned regions)
#define AH_OFF 0
#define AL_OFF 16384
#define BH_OFF 32768
#define BL_OFF 40960

// ---------------------------------------------------------------------------
// prep_w: wq/wk/wv/wp fp32 [256,256] -> bf16 hi/lo [1024,256]
// ---------------------------------------------------------------------------
__global__ __launch_bounds__(256) void prep_w_kernel(
    const float* __restrict__ wq, const float* __restrict__ wk,
    const float* __restrict__ wv, const float* __restrict__ wp)
{
    const int t  = blockIdx.x * 256 + threadIdx.x;   // 0..65535
    const int r  = t >> 6;                            // 0..1023
    const int c4 = (t & 63) * 4;
    const float* w = (r < 256) ? wq : (r < 512) ? wk : (r < 768) ? wv : wp;
    const int lr = r & 255;
    float4 v = *(const float4*)(w + (size_t)lr * CC + c4);
    const float f[4] = {v.x, v.y, v.z, v.w};
    __nv_bfloat16 hi[4], lo[4];
#pragma unroll
    for (int i = 0; i < 4; i++) {
        hi[i] = __float2bfloat16(f[i]);
        lo[i] = __float2bfloat16(f[i] - __bfloat162float(hi[i]));
    }
    *(uint64_t*)&g_wh[(size_t)r * CC + c4] = *(const uint64_t*)hi;
    *(uint64_t*)&g_wl[(size_t)r * CC + c4] = *(const uint64_t*)lo;
}

// ---------------------------------------------------------------------------
// prep_x: x (B,C,HW) fp32 -> g_xh/g_xl bf16 [pix][C]
// ---------------------------------------------------------------------------
__global__ __launch_bounds__(256) void prep_x_kernel(const float* __restrict__ x)
{
    __shared__ float t[32][33];
    const int b = blockIdx.z, c0 = blockIdx.y * 32, hw0 = blockIdx.x * 32;
    const int tx = threadIdx.x & 31, ty = threadIdx.x >> 5;
    const float* xb = x + ((size_t)b * CC + c0) * HW_ + hw0;
#pragma unroll
    for (int r = 0; r < 4; r++)
        t[ty + r * 8][tx] = xb[(size_t)(ty + r * 8) * HW_ + tx];
    __syncthreads();
#pragma unroll
    for (int r = 0; r < 4; r++) {
        const int hw = ty + r * 8;
        const float f = t[tx][hw];
        const __nv_bfloat16 hi = __float2bfloat16(f);
        const __nv_bfloat16 lo = __float2bfloat16(f - __bfloat162float(hi));
        const size_t o = (size_t)(b * HW_ + hw0 + hw) * CC + c0 + tx;
        g_xh[o] = hi;
        g_xl[o] = lo;
    }
}

// ---------------------------------------------------------------------------
// GEMM core: C[128 pix x 64 n] += A[pix][k] * B[n][k], bf16-split, K=256.
// 8 warps as 4(m) x 2(n); warp tile 32x32; smem chunks of K=64.
// ---------------------------------------------------------------------------
__device__ __forceinline__ void gemm_core(
    const __nv_bfloat16* __restrict__ Ah, const __nv_bfloat16* __restrict__ Al,
    const __nv_bfloat16* __restrict__ Bh, const __nv_bfloat16* __restrict__ Bl,
    int pix0, int n0, char* smg, uint32_t sb, float acc[2][4][4])
{
    const int tid  = threadIdx.x;
    const int lane = tid & 31;
    const int wid  = tid >> 5;
    const int wm   = wid & 3;
    const int wn   = wid >> 2;

    const int r8  = lane & 7, sel = lane >> 3;
    const uint32_t a_row = (uint32_t)((sel & 1) * 8 + r8);
    const uint32_t a_kbo = (uint32_t)((sel >> 1) * 16);
    const uint32_t b_row = (uint32_t)((sel >> 1) * 8 + r8);
    const uint32_t b_kbo = (uint32_t)((sel & 1) * 16);

    for (int kc = 0; kc < 4; kc++) {
        const int k0 = kc * 64;
        if (kc) __syncthreads();
#pragma unroll
        for (int i = 0; i < 4; i++) {
            const int idx = tid + i * 256;
            const int row = idx >> 3, seg = idx & 7;
            const uint32_t d = SW128((uint32_t)(row * 128 + seg * 16));
            const size_t  s = (size_t)(pix0 + row) * CC + k0 + seg * 8;
            *(uint4*)(smg + AH_OFF + d) = *(const uint4*)(Ah + s);
            *(uint4*)(smg + AL_OFF + d) = *(const uint4*)(Al + s);
        }
#pragma unroll
        for (int i = 0; i < 2; i++) {
            const int idx = tid + i * 256;
            const int row = idx >> 3, seg = idx & 7;
            const uint32_t d = SW128((uint32_t)(row * 128 + seg * 16));
            const size_t  s = (size_t)(n0 + row) * CC + k0 + seg * 8;
            *(uint4*)(smg + BH_OFF + d) = *(const uint4*)(Bh + s);
            *(uint4*)(smg + BL_OFF + d) = *(const uint4*)(Bl + s);
        }
        __syncthreads();

#pragma unroll
        for (int kk = 0; kk < 4; kk++) {
            uint32_t ah[2][4], al[2][4], bh[4][2], bl[4][2];
#pragma unroll
            for (int mi = 0; mi < 2; mi++) {
                const uint32_t off =
                    (uint32_t)((wm * 32 + mi * 16 + a_row) * 128) + kk * 32 + a_kbo;
                ldsm_x4(ah[mi], sb + AH_OFF + SW128(off));
                ldsm_x4(al[mi], sb + AL_OFF + SW128(off));
            }
#pragma unroll
            for (int np = 0; np < 2; np++) {
                const uint32_t off =
                    (uint32_t)((wn * 32 + np * 16 + b_row) * 128) + kk * 32 + b_kbo;
                uint32_t r[4];
                ldsm_x4(r, sb + BH_OFF + SW128(off));
                bh[np * 2][0] = r[0]; bh[np * 2][1] = r[1];
                bh[np * 2 + 1][0] = r[2]; bh[np * 2 + 1][1] = r[3];
                ldsm_x4(r, sb + BL_OFF + SW128(off));
                bl[np * 2][0] = r[0]; bl[np * 2][1] = r[1];
                bl[np * 2 + 1][0] = r[2]; bl[np * 2 + 1][1] = r[3];
            }
#pragma unroll
            for (int mi = 0; mi < 2; mi++)
#pragma unroll
                for (int ni = 0; ni < 4; ni++) {
                    mma_bf16(acc[mi][ni], ah[mi], bh[ni], acc[mi][ni]);
                    mma_bf16(acc[mi][ni], ah[mi], bl[ni], acc[mi][ni]);
                    mma_bf16(acc[mi][ni], al[mi], bh[ni], acc[mi][ni]);
                }
        }
    }
}

// ---------------------------------------------------------------------------
// QKV GEMM: out fp32 [pix][C], q pre-scaled
// ---------------------------------------------------------------------------
__global__ __launch_bounds__(256) void qkv_gemm_kernel()
{
    __shared__ __align__(1024) char smg[49152];
    const uint32_t sb = smem_u32(smg);
    const int pix0 = blockIdx.x * 128;
    const int n0   = blockIdx.y * 64;
    const int m    = blockIdx.z;

    const __nv_bfloat16* Bh = g_wh + (size_t)m * CC * CC;
    const __nv_bfloat16* Bl = g_wl + (size_t)m * CC * CC;

    float acc[2][4][4] = {};
    gemm_core(g_xh, g_xl, Bh, Bl, pix0, n0, smg, sb, acc);

    float* out = (m == 0) ? g_q : (m == 1) ? g_k : g_v;
    const float qs = (m == 0) ? 0.17677669529663687f : 1.0f;

    const int tid = threadIdx.x, lane = tid & 31, wid = tid >> 5;
    const int wm = wid & 3, wn = wid >> 2;
    const int g = lane >> 2, tig = lane & 3;
#pragma unroll
    for (int mi = 0; mi < 2; mi++)
#pragma unroll
        for (int ni = 0; ni < 4; ni++) {
            const int mm = pix0 + wm * 32 + mi * 16 + g;
            const int nn = n0 + wn * 32 + ni * 8 + tig * 2;
            float2 v0 = {acc[mi][ni][0] * qs, acc[mi][ni][1] * qs};
            float2 v1 = {acc[mi][ni][2] * qs, acc[mi][ni][3] * qs};
            *(float2*)(out + (size_t)mm * CC + nn) = v0;
            *(float2*)(out + (size_t)(mm + 8) * CC + nn) = v1;
        }
}

// ---------------------------------------------------------------------------
// Proj GEMM: y[b][o][hw] = sum_c oh/ol * wp + bias, smem-transposed stores
// ---------------------------------------------------------------------------
__global__ __launch_bounds__(256) void proj_gemm_kernel(
    const float* __restrict__ bp, float* __restrict__ y)
{
    __shared__ __align__(1024) char smg[49152];
    const uint32_t sb = smem_u32(smg);
    const int pix0 = blockIdx.x * 128;
    const int n0   = blockIdx.y * 64;

    const __nv_bfloat16* Bh = g_wh + (size_t)3 * CC * CC;
    const __nv_bfloat16* Bl = g_wl + (size_t)3 * CC * CC;

    float acc[2][4][4] = {};
    gemm_core(g_oh, g_ol, Bh, Bl, pix0, n0, smg, sb, acc);

    __syncthreads();
    float (*buf)[136] = (float(*)[136])smg;   // 64 x 136 fp32 = 34816B

    const int tid = threadIdx.x, lane = tid & 31, wid = tid >> 5;
    const int wm = wid & 3, wn = wid >> 2;
    const int g = lane >> 2, tig = lane & 3;
#pragma unroll
    for (int mi = 0; mi < 2; mi++)
#pragma unroll
        for (int ni = 0; ni < 4; ni++) {
            const int ml = wm * 32 + mi * 16 + g;
            const int nl = wn * 32 + ni * 8 + tig * 2;
            buf[nl][ml]         = acc[mi][ni][0];
            buf[nl + 1][ml]     = acc[mi][ni][1];
            buf[nl][ml + 8]     = acc[mi][ni][2];
            buf[nl + 1][ml + 8] = acc[mi][ni][3];
        }
    __syncthreads();

    const int b = pix0 / HW_;
    const int hw0 = pix0 % HW_;
#pragma unroll
    for (int it = 0; it < 8; it++) {
        const int idx = tid + it * 256;
        const int o = idx >> 5;
        const int hq = (idx & 31) * 4;
        float4 v = *(float4*)&buf[o][hq];
        const float bv = bp[n0 + o];
        v.x += bv; v.y += bv; v.z += bv; v.w += bv;
        *(float4*)(y + (size_t)b * CC * HW_ + (size_t)(n0 + o) * HW_ + hw0 + hq) = v;
    }
}

// ---------------------------------------------------------------------------
// Neighborhood attention; epilogue emits bf16 hi/lo for the proj GEMM
// ---------------------------------------------------------------------------
extern __shared__ float sm_attn[];

__global__ __launch_bounds__(256) void attn_kernel(const float* __restrict__ rpb)
{
    float* ks = sm_attn;
    float* vs = sm_attn + ER * ER * PSTR;
    float* rs = vs + ER * ER * PSTR;

    const int tile = blockIdx.x;
    const int head = blockIdx.y;
    const int b    = blockIdx.z;
    const int i0   = (tile / (WW / TJ)) * TI;
    const int j0   = (tile % (WW / TJ)) * TJ;
    const int tid  = threadIdx.x;

    const int rb = min(max(i0 - 3, 0), HH - KW);
    const int cb = min(max(j0 - 3, 0), WW - KW);

    const float* kbase = g_k + (size_t)b * HW_ * CC + head * HD;
    const float* vbase = g_v + (size_t)b * HW_ * CC + head * HD;

    for (int t = tid; t < ER * ER * 8; t += 256) {
        const int pix = t >> 3, d4 = t & 7;
        const int rr = min(rb + pix / ER, HH - 1);
        const int cc = min(cb + pix % ER, WW - 1);
        const size_t go = (size_t)(rr * WW + cc) * CC + d4 * 4;
        *(float4*)&ks[pix * PSTR + d4 * 4] = *(const float4*)(kbase + go);
        *(float4*)&vs[pix * PSTR + d4 * 4] = *(const float4*)(vbase + go);
    }
    if (tid < 169) rs[tid] = rpb[head * 169 + tid];
    __syncthreads();

    const int ti = tid >> 4, tj = tid & 15;
    const int i = i0 + ti, j = j0 + tj;
    const int sh = min(max(i - 3, 0), HH - KW);
    const int sw = min(max(j - 3, 0), WW - KW);
    const int dbi = sh - i + 6, dbj = sw - j + 6;
    const int prow = sh - rb, pcol = sw - cb;

    const float* qp = g_q + ((size_t)(b * HW_) + i * WW + j) * CC + head * HD;
    float4 q[8];
#pragma unroll
    for (int d = 0; d < 8; d++) q[d] = *(const float4*)(qp + d * 4);

    float lg[49];
    float mx = -1e30f;
#pragma unroll
    for (int ki = 0; ki < KW; ki++) {
#pragma unroll
        for (int kj = 0; kj < KW; kj++) {
            const float* kp = &ks[((prow + ki) * ER + pcol + kj) * PSTR];
            float acc = 0.f;
#pragma unroll
            for (int d = 0; d < 8; d++) {
                float4 kv = *(const float4*)(kp + d * 4);
                acc += q[d].x * kv.x + q[d].y * kv.y +
                       q[d].z * kv.z + q[d].w * kv.w;
            }
            acc += rs[(dbi + ki) * 13 + (dbj + kj)];
            lg[ki * KW + kj] = acc;
            mx = fmaxf(mx, acc);
        }
    }

    float s = 0.f;
#pragma unroll
    for (int n = 0; n < 49; n++) {
        float e = __expf(lg[n] - mx);
        lg[n] = e;
        s += e;
    }
    const float inv = 1.0f / s;

    float4 o[8];
#pragma unroll
    for (int d = 0; d < 8; d++) o[d] = make_float4(0.f, 0.f, 0.f, 0.f);

#pragma unroll
    for (int ki = 0; ki < KW; ki++) {
#pragma unroll
        for (int kj = 0; kj < KW; kj++) {
            const float w = lg[ki * KW + kj];
            const float* vp = &vs[((prow + ki) * ER + pcol + kj) * PSTR];
#pragma unroll
            for (int d = 0; d < 8; d++) {
                float4 vv = *(const float4*)(vp + d * 4);
                o[d].x += w * vv.x; o[d].y += w * vv.y;
                o[d].z += w * vv.z; o[d].w += w * vv.w;
            }
        }
    }

    // Emit bf16 hi/lo for the proj GEMM
    __nv_bfloat16 hi[32], lo[32];
#pragma unroll
    for (int d = 0; d < 8; d++) {
        const float vals[4] = {o[d].x * inv, o[d].y * inv,
                               o[d].z * inv, o[d].w * inv};
#pragma unroll
        for (int c = 0; c < 4; c++) {
            const __nv_bfloat16 h = __float2bfloat16(vals[c]);
            hi[d * 4 + c] = h;
            lo[d * 4 + c] = __float2bfloat16(vals[c] - __bfloat162float(h));
        }
    }
    const size_t ob = ((size_t)(b * HW_) + i * WW + j) * CC + head * HD;
#pragma unroll
    for (int u = 0; u < 4; u++) {
        *(uint4*)(g_oh + ob + u * 8) = *(const uint4*)&hi[u * 8];
        *(uint4*)(g_ol + ob + u * 8) = *(const uint4*)&lo[u * 8];
    }
}

// ---------------------------------------------------------------------------
extern "C" void kernel_launch(void* const* d_in, const int* in_sizes, int n_in,
                              void* d_out, int out_size)
{
    const float* x   = (const float*)d_in[0];
    const float* wq  = (const float*)d_in[1];
    const float* wk  = (const float*)d_in[2];
    const float* wv  = (const float*)d_in[3];
    const float* wp  = (const float*)d_in[4];
    const float* bp  = (const float*)d_in[5];
    const float* rpb = (const float*)d_in[6];
    float* y = (float*)d_out;

    prep_w_kernel<<<256, 256>>>(wq, wk, wv, wp);
    prep_x_kernel<<<dim3(HW_ / 32, CC / 32, BB), 256>>>(x);

    qkv_gemm_kernel<<<dim3(NPIX / 128, CC / 64, 3), 256>>>();

    const int smem_bytes = (2 * ER * ER * PSTR + 169) * (int)sizeof(float);
    (void)cudaFuncSetAttribute(attn_kernel,
                               cudaFuncAttributeMaxDynamicSharedMemorySize,
                               smem_bytes);
    attn_kernel<<<dim3((HH / TI) * (WW / TJ), HEADS, BB), 256, smem_bytes>>>(rpb);

    proj_gemm_kernel<<<dim3(NPIX / 128, CC / 64), 256>>>(bp, y);
}

// round 6
// speedup vs baseline: 2.1419x; 1.2360x over previous
#include <cuda_runtime.h>
#include <cuda_bf16.h>
#include <cuda_fp16.h>
#include <cstdint>

// Problem constants
#define BB    8
#define CC    256
#define HH    96
#define WW    96
#define HEADS 8
#define HD    32
#define KW    7
#define HW_   (HH * WW)          // 9216
#define NPIX  (BB * HW_)         // 73728

// Attention tiling
#define TI   16
#define TJ   16
#define ER   22                  // halo edge
#define KSTR 40                  // smem pixel stride in halfs (80 bytes)

// Scratch
__device__ float g_q[(size_t)NPIX * CC];
__device__ __half g_kh[(size_t)NPIX * CC];
__device__ __half g_vh[(size_t)NPIX * CC];

// bf16 split operands
__device__ __nv_bfloat16 g_xh[(size_t)NPIX * CC];
__device__ __nv_bfloat16 g_xl[(size_t)NPIX * CC];
__device__ __nv_bfloat16 g_oh[(size_t)NPIX * CC];
__device__ __nv_bfloat16 g_ol[(size_t)NPIX * CC];
__device__ __nv_bfloat16 g_wh[4 * CC * CC];
__device__ __nv_bfloat16 g_wl[4 * CC * CC];

// ---------------------------------------------------------------------------
// Helpers
// ---------------------------------------------------------------------------
__device__ __forceinline__ uint32_t smem_u32(const void* p) {
    uint32_t a;
    asm("{ .reg .u64 t; cvta.to.shared.u64 t, %1; cvt.u32.u64 %0, t; }"
        : "=r"(a) : "l"(p));
    return a;
}

__device__ __forceinline__ void ldsm_x4(uint32_t* r, uint32_t addr) {
    asm volatile("ldmatrix.sync.aligned.m8n8.x4.shared.b16 {%0,%1,%2,%3}, [%4];"
        : "=r"(r[0]), "=r"(r[1]), "=r"(r[2]), "=r"(r[3]) : "r"(addr));
}

__device__ __forceinline__ void mma_bf16(float* d, const uint32_t* a,
                                         const uint32_t* b, const float* c) {
    asm volatile(
        "mma.sync.aligned.m16n8k16.row.col.f32.bf16.bf16.f32 "
        "{%0,%1,%2,%3}, {%4,%5,%6,%7}, {%8,%9}, {%10,%11,%12,%13};"
        : "=f"(d[0]), "=f"(d[1]), "=f"(d[2]), "=f"(d[3])
        : "r"(a[0]), "r"(a[1]), "r"(a[2]), "r"(a[3]),
          "r"(b[0]), "r"(b[1]),
          "f"(c[0]), "f"(c[1]), "f"(c[2]), "f"(c[3]));
}

#define SW128(o) ((o) ^ (((o) >> 3) & 0x70))

// smem layout for gemm kernels
#define AH_OFF 0
#define AL_OFF 16384
#define BH_OFF 32768
#define BL_OFF 40960

// ---------------------------------------------------------------------------
// prep_w: wq/wk/wv/wp fp32 [256,256] -> bf16 hi/lo [1024,256]
// ---------------------------------------------------------------------------
__global__ __launch_bounds__(256) void prep_w_kernel(
    const float* __restrict__ wq, const float* __restrict__ wk,
    const float* __restrict__ wv, const float* __restrict__ wp)
{
    const int t  = blockIdx.x * 256 + threadIdx.x;
    const int r  = t >> 6;
    const int c4 = (t & 63) * 4;
    const float* w = (r < 256) ? wq : (r < 512) ? wk : (r < 768) ? wv : wp;
    const int lr = r & 255;
    float4 v = *(const float4*)(w + (size_t)lr * CC + c4);
    const float f[4] = {v.x, v.y, v.z, v.w};
    __nv_bfloat16 hi[4], lo[4];
#pragma unroll
    for (int i = 0; i < 4; i++) {
        hi[i] = __float2bfloat16(f[i]);
        lo[i] = __float2bfloat16(f[i] - __bfloat162float(hi[i]));
    }
    *(uint64_t*)&g_wh[(size_t)r * CC + c4] = *(const uint64_t*)hi;
    *(uint64_t*)&g_wl[(size_t)r * CC + c4] = *(const uint64_t*)lo;
}

// ---------------------------------------------------------------------------
// prep_x: x (B,C,HW) fp32 -> g_xh/g_xl bf16 [pix][C]
// ---------------------------------------------------------------------------
__global__ __launch_bounds__(256) void prep_x_kernel(const float* __restrict__ x)
{
    __shared__ float t[32][33];
    const int b = blockIdx.z, c0 = blockIdx.y * 32, hw0 = blockIdx.x * 32;
    const int tx = threadIdx.x & 31, ty = threadIdx.x >> 5;
    const float* xb = x + ((size_t)b * CC + c0) * HW_ + hw0;
#pragma unroll
    for (int r = 0; r < 4; r++)
        t[ty + r * 8][tx] = xb[(size_t)(ty + r * 8) * HW_ + tx];
    __syncthreads();
#pragma unroll
    for (int r = 0; r < 4; r++) {
        const int hw = ty + r * 8;
        const float f = t[tx][hw];
        const __nv_bfloat16 hi = __float2bfloat16(f);
        const __nv_bfloat16 lo = __float2bfloat16(f - __bfloat162float(hi));
        const size_t o = (size_t)(b * HW_ + hw0 + hw) * CC + c0 + tx;
        g_xh[o] = hi;
        g_xl[o] = lo;
    }
}

// ---------------------------------------------------------------------------
// GEMM core: C[128 pix x 64 n] += A[pix][k] * B[n][k], bf16-split, K=256.
// ---------------------------------------------------------------------------
__device__ __forceinline__ void gemm_core(
    const __nv_bfloat16* __restrict__ Ah, const __nv_bfloat16* __restrict__ Al,
    const __nv_bfloat16* __restrict__ Bh, const __nv_bfloat16* __restrict__ Bl,
    int pix0, int n0, char* smg, uint32_t sb, float acc[2][4][4])
{
    const int tid  = threadIdx.x;
    const int lane = tid & 31;
    const int wid  = tid >> 5;
    const int wm   = wid & 3;
    const int wn   = wid >> 2;

    const int r8  = lane & 7, sel = lane >> 3;
    const uint32_t a_row = (uint32_t)((sel & 1) * 8 + r8);
    const uint32_t a_kbo = (uint32_t)((sel >> 1) * 16);
    const uint32_t b_row = (uint32_t)((sel >> 1) * 8 + r8);
    const uint32_t b_kbo = (uint32_t)((sel & 1) * 16);

    for (int kc = 0; kc < 4; kc++) {
        const int k0 = kc * 64;
        if (kc) __syncthreads();
#pragma unroll
        for (int i = 0; i < 4; i++) {
            const int idx = tid + i * 256;
            const int row = idx >> 3, seg = idx & 7;
            const uint32_t d = SW128((uint32_t)(row * 128 + seg * 16));
            const size_t  s = (size_t)(pix0 + row) * CC + k0 + seg * 8;
            *(uint4*)(smg + AH_OFF + d) = *(const uint4*)(Ah + s);
            *(uint4*)(smg + AL_OFF + d) = *(const uint4*)(Al + s);
        }
#pragma unroll
        for (int i = 0; i < 2; i++) {
            const int idx = tid + i * 256;
            const int row = idx >> 3, seg = idx & 7;
            const uint32_t d = SW128((uint32_t)(row * 128 + seg * 16));
            const size_t  s = (size_t)(n0 + row) * CC + k0 + seg * 8;
            *(uint4*)(smg + BH_OFF + d) = *(const uint4*)(Bh + s);
            *(uint4*)(smg + BL_OFF + d) = *(const uint4*)(Bl + s);
        }
        __syncthreads();

#pragma unroll
        for (int kk = 0; kk < 4; kk++) {
            uint32_t ah[2][4], al[2][4], bh[4][2], bl[4][2];
#pragma unroll
            for (int mi = 0; mi < 2; mi++) {
                const uint32_t off =
                    (uint32_t)((wm * 32 + mi * 16 + a_row) * 128) + kk * 32 + a_kbo;
                ldsm_x4(ah[mi], sb + AH_OFF + SW128(off));
                ldsm_x4(al[mi], sb + AL_OFF + SW128(off));
            }
#pragma unroll
            for (int np = 0; np < 2; np++) {
                const uint32_t off =
                    (uint32_t)((wn * 32 + np * 16 + b_row) * 128) + kk * 32 + b_kbo;
                uint32_t r[4];
                ldsm_x4(r, sb + BH_OFF + SW128(off));
                bh[np * 2][0] = r[0]; bh[np * 2][1] = r[1];
                bh[np * 2 + 1][0] = r[2]; bh[np * 2 + 1][1] = r[3];
                ldsm_x4(r, sb + BL_OFF + SW128(off));
                bl[np * 2][0] = r[0]; bl[np * 2][1] = r[1];
                bl[np * 2 + 1][0] = r[2]; bl[np * 2 + 1][1] = r[3];
            }
#pragma unroll
            for (int mi = 0; mi < 2; mi++)
#pragma unroll
                for (int ni = 0; ni < 4; ni++) {
                    mma_bf16(acc[mi][ni], ah[mi], bh[ni], acc[mi][ni]);
                    mma_bf16(acc[mi][ni], ah[mi], bl[ni], acc[mi][ni]);
                    mma_bf16(acc[mi][ni], al[mi], bh[ni], acc[mi][ni]);
                }
        }
    }
}

// ---------------------------------------------------------------------------
// QKV GEMM: q -> fp32 (pre-scaled); k, v -> fp16
// ---------------------------------------------------------------------------
__global__ __launch_bounds__(256) void qkv_gemm_kernel()
{
    __shared__ __align__(1024) char smg[49152];
    const uint32_t sb = smem_u32(smg);
    const int pix0 = blockIdx.x * 128;
    const int n0   = blockIdx.y * 64;
    const int m    = blockIdx.z;

    const __nv_bfloat16* Bh = g_wh + (size_t)m * CC * CC;
    const __nv_bfloat16* Bl = g_wl + (size_t)m * CC * CC;

    float acc[2][4][4] = {};
    gemm_core(g_xh, g_xl, Bh, Bl, pix0, n0, smg, sb, acc);

    const int tid = threadIdx.x, lane = tid & 31, wid = tid >> 5;
    const int wm = wid & 3, wn = wid >> 2;
    const int g = lane >> 2, tig = lane & 3;

    if (m == 0) {
        const float qs = 0.17677669529663687f;
#pragma unroll
        for (int mi = 0; mi < 2; mi++)
#pragma unroll
            for (int ni = 0; ni < 4; ni++) {
                const int mm = pix0 + wm * 32 + mi * 16 + g;
                const int nn = n0 + wn * 32 + ni * 8 + tig * 2;
                float2 v0 = {acc[mi][ni][0] * qs, acc[mi][ni][1] * qs};
                float2 v1 = {acc[mi][ni][2] * qs, acc[mi][ni][3] * qs};
                *(float2*)(g_q + (size_t)mm * CC + nn) = v0;
                *(float2*)(g_q + (size_t)(mm + 8) * CC + nn) = v1;
            }
    } else {
        __half* out = (m == 1) ? g_kh : g_vh;
#pragma unroll
        for (int mi = 0; mi < 2; mi++)
#pragma unroll
            for (int ni = 0; ni < 4; ni++) {
                const int mm = pix0 + wm * 32 + mi * 16 + g;
                const int nn = n0 + wn * 32 + ni * 8 + tig * 2;
                __half2 v0 = {__float2half_rn(acc[mi][ni][0]),
                              __float2half_rn(acc[mi][ni][1])};
                __half2 v1 = {__float2half_rn(acc[mi][ni][2]),
                              __float2half_rn(acc[mi][ni][3])};
                *(__half2*)(out + (size_t)mm * CC + nn) = v0;
                *(__half2*)(out + (size_t)(mm + 8) * CC + nn) = v1;
            }
    }
}

// ---------------------------------------------------------------------------
// Proj GEMM
// ---------------------------------------------------------------------------
__global__ __launch_bounds__(256) void proj_gemm_kernel(
    const float* __restrict__ bp, float* __restrict__ y)
{
    __shared__ __align__(1024) char smg[49152];
    const uint32_t sb = smem_u32(smg);
    const int pix0 = blockIdx.x * 128;
    const int n0   = blockIdx.y * 64;

    const __nv_bfloat16* Bh = g_wh + (size_t)3 * CC * CC;
    const __nv_bfloat16* Bl = g_wl + (size_t)3 * CC * CC;

    float acc[2][4][4] = {};
    gemm_core(g_oh, g_ol, Bh, Bl, pix0, n0, smg, sb, acc);

    __syncthreads();
    float (*buf)[136] = (float(*)[136])smg;

    const int tid = threadIdx.x, lane = tid & 31, wid = tid >> 5;
    const int wm = wid & 3, wn = wid >> 2;
    const int g = lane >> 2, tig = lane & 3;
#pragma unroll
    for (int mi = 0; mi < 2; mi++)
#pragma unroll
        for (int ni = 0; ni < 4; ni++) {
            const int ml = wm * 32 + mi * 16 + g;
            const int nl = wn * 32 + ni * 8 + tig * 2;
            buf[nl][ml]         = acc[mi][ni][0];
            buf[nl + 1][ml]     = acc[mi][ni][1];
            buf[nl][ml + 8]     = acc[mi][ni][2];
            buf[nl + 1][ml + 8] = acc[mi][ni][3];
        }
    __syncthreads();

    const int b = pix0 / HW_;
    const int hw0 = pix0 % HW_;
#pragma unroll
    for (int it = 0; it < 8; it++) {
        const int idx = tid + it * 256;
        const int o = idx >> 5;
        const int hq = (idx & 31) * 4;
        float4 v = *(float4*)&buf[o][hq];
        const float bv = bp[n0 + o];
        v.x += bv; v.y += bv; v.z += bv; v.w += bv;
        *(float4*)(y + (size_t)b * CC * HW_ + (size_t)(n0 + o) * HW_ + hw0 + hq) = v;
    }
}

// ---------------------------------------------------------------------------
// Neighborhood attention: fp16 k/v halos in smem (80B pixel stride)
// ---------------------------------------------------------------------------
extern __shared__ __align__(16) char sm_raw[];

__global__ __launch_bounds__(256) void attn_kernel(const float* __restrict__ rpb)
{
    __half* ks = (__half*)sm_raw;
    __half* vs = ks + ER * ER * KSTR;
    float*  rs = (float*)(vs + ER * ER * KSTR);   // 169 floats

    const int tile = blockIdx.x;
    const int head = blockIdx.y;
    const int b    = blockIdx.z;
    const int i0   = (tile / (WW / TJ)) * TI;
    const int j0   = (tile % (WW / TJ)) * TJ;
    const int tid  = threadIdx.x;

    const int rb = min(max(i0 - 3, 0), HH - KW);
    const int cb = min(max(j0 - 3, 0), WW - KW);

    const __half* kbase = g_kh + (size_t)b * HW_ * CC + head * HD;
    const __half* vbase = g_vh + (size_t)b * HW_ * CC + head * HD;

    // Stage 22x22 halo: per pixel 32 halfs = 4 x uint4
    for (int t = tid; t < ER * ER * 4; t += 256) {
        const int pix = t >> 2, seg = t & 3;
        const int rr = min(rb + pix / ER, HH - 1);
        const int cc = min(cb + pix % ER, WW - 1);
        const size_t go = (size_t)(rr * WW + cc) * CC + seg * 8;
        *(uint4*)&ks[pix * KSTR + seg * 8] = *(const uint4*)(kbase + go);
        *(uint4*)&vs[pix * KSTR + seg * 8] = *(const uint4*)(vbase + go);
    }
    if (tid < 169) rs[tid] = rpb[head * 169 + tid];
    __syncthreads();

    const int ti = tid >> 4, tj = tid & 15;
    const int i = i0 + ti, j = j0 + tj;
    const int sh = min(max(i - 3, 0), HH - KW);
    const int sw = min(max(j - 3, 0), WW - KW);
    const int dbi = sh - i + 6, dbj = sw - j + 6;
    const int prow = sh - rb, pcol = sw - cb;

    const float* qp = g_q + ((size_t)(b * HW_) + i * WW + j) * CC + head * HD;
    float q[32];
#pragma unroll
    for (int d = 0; d < 8; d++)
        *(float4*)&q[d * 4] = *(const float4*)(qp + d * 4);

    float lg[49];
    float mx = -1e30f;
#pragma unroll
    for (int ki = 0; ki < KW; ki++) {
#pragma unroll
        for (int kj = 0; kj < KW; kj++) {
            const __half* kp = &ks[((prow + ki) * ER + pcol + kj) * KSTR];
            float acc = 0.f;
#pragma unroll
            for (int s = 0; s < 4; s++) {
                uint4 w = *(const uint4*)(kp + s * 8);
                const uint32_t ww[4] = {w.x, w.y, w.z, w.w};
#pragma unroll
                for (int u = 0; u < 4; u++) {
                    float2 kv = __half22float2(*(const __half2*)&ww[u]);
                    acc += q[s * 8 + u * 2] * kv.x + q[s * 8 + u * 2 + 1] * kv.y;
                }
            }
            acc += rs[(dbi + ki) * 13 + (dbj + kj)];
            lg[ki * KW + kj] = acc;
            mx = fmaxf(mx, acc);
        }
    }

    float s = 0.f;
#pragma unroll
    for (int n = 0; n < 49; n++) {
        float e = __expf(lg[n] - mx);
        lg[n] = e;
        s += e;
    }
    const float inv = 1.0f / s;

    float o[32];
#pragma unroll
    for (int d = 0; d < 32; d++) o[d] = 0.f;

#pragma unroll
    for (int ki = 0; ki < KW; ki++) {
#pragma unroll
        for (int kj = 0; kj < KW; kj++) {
            const float w = lg[ki * KW + kj];
            const __half* vp = &vs[((prow + ki) * ER + pcol + kj) * KSTR];
#pragma unroll
            for (int sg = 0; sg < 4; sg++) {
                uint4 wv = *(const uint4*)(vp + sg * 8);
                const uint32_t ww[4] = {wv.x, wv.y, wv.z, wv.w};
#pragma unroll
                for (int u = 0; u < 4; u++) {
                    float2 vv = __half22float2(*(const __half2*)&ww[u]);
                    o[sg * 8 + u * 2]     += w * vv.x;
                    o[sg * 8 + u * 2 + 1] += w * vv.y;
                }
            }
        }
    }

    // Emit bf16 hi/lo for the proj GEMM
    __nv_bfloat16 hi[32], lo[32];
#pragma unroll
    for (int c = 0; c < 32; c++) {
        const float v = o[c] * inv;
        const __nv_bfloat16 h = __float2bfloat16(v);
        hi[c] = h;
        lo[c] = __float2bfloat16(v - __bfloat162float(h));
    }
    const size_t ob = ((size_t)(b * HW_) + i * WW + j) * CC + head * HD;
#pragma unroll
    for (int u = 0; u < 4; u++) {
        *(uint4*)(g_oh + ob + u * 8) = *(const uint4*)&hi[u * 8];
        *(uint4*)(g_ol + ob + u * 8) = *(const uint4*)&lo[u * 8];
    }
}

// ---------------------------------------------------------------------------
extern "C" void kernel_launch(void* const* d_in, const int* in_sizes, int n_in,
                              void* d_out, int out_size)
{
    const float* x   = (const float*)d_in[0];
    const float* wq  = (const float*)d_in[1];
    const float* wk  = (const float*)d_in[2];
    const float* wv  = (const float*)d_in[3];
    const float* wp  = (const float*)d_in[4];
    const float* bp  = (const float*)d_in[5];
    const float* rpb = (const float*)d_in[6];
    float* y = (float*)d_out;

    prep_w_kernel<<<256, 256>>>(wq, wk, wv, wp);
    prep_x_kernel<<<dim3(HW_ / 32, CC / 32, BB), 256>>>(x);

    qkv_gemm_kernel<<<dim3(NPIX / 128, CC / 64, 3), 256>>>();

    const int smem_bytes = 2 * ER * ER * KSTR * 2 + 169 * 4;   // ~78 KB
    (void)cudaFuncSetAttribute(attn_kernel,
                               cudaFuncAttributeMaxDynamicSharedMemorySize,
                               smem_bytes);
    attn_kernel<<<dim3((HH / TI) * (WW / TJ), HEADS, BB), 256, smem_bytes>>>(rpb);

    proj_gemm_kernel<<<dim3(NPIX / 128, CC / 64), 256>>>(bp, y);
}

// round 12
// speedup vs baseline: 3.0295x; 1.4144x over previous
#include <cuda_runtime.h>
#include <cuda_fp16.h>
#include <cstdint>

// Problem constants
#define BB    8
#define CC    256
#define HH    96
#define WW    96
#define HEADS 8
#define HD    32
#define KW    7
#define HW_   (HH * WW)          // 9216
#define NPIX  (BB * HW_)         // 73728

// Attention tiling
#define TI   16
#define TJ   16
#define ER   22                  // halo edge
#define KSTR 40                  // smem pixel stride in halfs (80 bytes)

// Scratch
__device__ float  g_q [(size_t)NPIX * CC];
__device__ __half g_kh[(size_t)NPIX * CC];
__device__ __half g_vh[(size_t)NPIX * CC];
__device__ __half g_xh[(size_t)NPIX * CC];
__device__ __half g_oh[(size_t)NPIX * CC];
__device__ __half g_w [4 * CC * CC];

// ---------------------------------------------------------------------------
// Helpers
// ---------------------------------------------------------------------------
__device__ __forceinline__ uint32_t smem_u32(const void* p) {
    uint32_t a;
    asm("{ .reg .u64 t; cvta.to.shared.u64 t, %1; cvt.u32.u64 %0, t; }"
        : "=r"(a) : "l"(p));
    return a;
}

__device__ __forceinline__ void ldsm_x4(uint32_t* r, uint32_t addr) {
    asm volatile("ldmatrix.sync.aligned.m8n8.x4.shared.b16 {%0,%1,%2,%3}, [%4];"
        : "=r"(r[0]), "=r"(r[1]), "=r"(r[2]), "=r"(r[3]) : "r"(addr));
}

__device__ __forceinline__ void mma_f16(float* d, const uint32_t* a,
                                        const uint32_t* b, const float* c) {
    asm volatile(
        "mma.sync.aligned.m16n8k16.row.col.f32.f16.f16.f32 "
        "{%0,%1,%2,%3}, {%4,%5,%6,%7}, {%8,%9}, {%10,%11,%12,%13};"
        : "=f"(d[0]), "=f"(d[1]), "=f"(d[2]), "=f"(d[3])
        : "r"(a[0]), "r"(a[1]), "r"(a[2]), "r"(a[3]),
          "r"(b[0]), "r"(b[1]),
          "f"(c[0]), "f"(c[1]), "f"(c[2]), "f"(c[3]));
}

#define SW128(o) ((o) ^ (((o) >> 3) & 0x70))

// smem layout for gemm kernels
#define A_OFF 0
#define B_OFF 16384

// ---------------------------------------------------------------------------
// prep_w: wq/wk/wv/wp fp32 [256,256] -> fp16 [1024,256]
// ---------------------------------------------------------------------------
__global__ __launch_bounds__(256) void prep_w_kernel(
    const float* __restrict__ wq, const float* __restrict__ wk,
    const float* __restrict__ wv, const float* __restrict__ wp)
{
    const int t  = blockIdx.x * 256 + threadIdx.x;
    const int r  = t >> 6;
    const int c4 = (t & 63) * 4;
    const float* w = (r < 256) ? wq : (r < 512) ? wk : (r < 768) ? wv : wp;
    const int lr = r & 255;
    float4 v = *(const float4*)(w + (size_t)lr * CC + c4);
    __half h[4] = {__float2half_rn(v.x), __float2half_rn(v.y),
                   __float2half_rn(v.z), __float2half_rn(v.w)};
    *(uint64_t*)&g_w[(size_t)r * CC + c4] = *(const uint64_t*)h;
}

// ---------------------------------------------------------------------------
// prep_x: x (B,C,HW) fp32 -> g_xh fp16 [pix][C]
// ---------------------------------------------------------------------------
__global__ __launch_bounds__(256) void prep_x_kernel(const float* __restrict__ x)
{
    __shared__ float t[32][33];
    const int b = blockIdx.z, c0 = blockIdx.y * 32, hw0 = blockIdx.x * 32;
    const int tx = threadIdx.x & 31, ty = threadIdx.x >> 5;
    const float* xb = x + ((size_t)b * CC + c0) * HW_ + hw0;
#pragma unroll
    for (int r = 0; r < 4; r++)
        t[ty + r * 8][tx] = xb[(size_t)(ty + r * 8) * HW_ + tx];
    __syncthreads();
#pragma unroll
    for (int r = 0; r < 4; r++) {
        const int hw = ty + r * 8;
        const size_t o = (size_t)(b * HW_ + hw0 + hw) * CC + c0 + tx;
        g_xh[o] = __float2half_rn(t[tx][hw]);
    }
}

// ---------------------------------------------------------------------------
// GEMM core: C[128 pix x 64 n] += A[pix][k] * B[n][k], fp16, K=256.
// 8 warps as 4(m) x 2(n); warp tile 32x32; smem chunks of K=64.
// ---------------------------------------------------------------------------
__device__ __forceinline__ void gemm_core(
    const __half* __restrict__ A, const __half* __restrict__ B,
    int pix0, int n0, char* smg, uint32_t sb, float acc[2][4][4])
{
    const int tid  = threadIdx.x;
    const int lane = tid & 31;
    const int wid  = tid >> 5;
    const int wm   = wid & 3;
    const int wn   = wid >> 2;

    const int r8  = lane & 7, sel = lane >> 3;
    const uint32_t a_row = (uint32_t)((sel & 1) * 8 + r8);
    const uint32_t a_kbo = (uint32_t)((sel >> 1) * 16);
    const uint32_t b_row = (uint32_t)((sel >> 1) * 8 + r8);
    const uint32_t b_kbo = (uint32_t)((sel & 1) * 16);

    for (int kc = 0; kc < 4; kc++) {
        const int k0 = kc * 64;
        if (kc) __syncthreads();
        // A tile: 128 rows x 64 halfs = 1024 uint4 -> 4 iterations
#pragma unroll
        for (int i = 0; i < 4; i++) {
            const int idx = tid + i * 256;
            const int row = idx >> 3, seg = idx & 7;
            const uint32_t d = SW128((uint32_t)(row * 128 + seg * 16));
            const size_t  s = (size_t)(pix0 + row) * CC + k0 + seg * 8;
            *(uint4*)(smg + A_OFF + d) = *(const uint4*)(A + s);
        }
        // B tile: 64 rows x 64 halfs = 512 uint4 -> 2 iterations
#pragma unroll
        for (int i = 0; i < 2; i++) {
            const int idx = tid + i * 256;
            const int row = idx >> 3, seg = idx & 7;
            const uint32_t d = SW128((uint32_t)(row * 128 + seg * 16));
            const size_t  s = (size_t)(n0 + row) * CC + k0 + seg * 8;
            *(uint4*)(smg + B_OFF + d) = *(const uint4*)(B + s);
        }
        __syncthreads();

#pragma unroll
        for (int kk = 0; kk < 4; kk++) {
            uint32_t a[2][4], b[4][2];
#pragma unroll
            for (int mi = 0; mi < 2; mi++) {
                const uint32_t off =
                    (uint32_t)((wm * 32 + mi * 16 + a_row) * 128) + kk * 32 + a_kbo;
                ldsm_x4(a[mi], sb + A_OFF + SW128(off));
            }
#pragma unroll
            for (int np = 0; np < 2; np++) {
                const uint32_t off =
                    (uint32_t)((wn * 32 + np * 16 + b_row) * 128) + kk * 32 + b_kbo;
                uint32_t r[4];
                ldsm_x4(r, sb + B_OFF + SW128(off));
                b[np * 2][0] = r[0]; b[np * 2][1] = r[1];
                b[np * 2 + 1][0] = r[2]; b[np * 2 + 1][1] = r[3];
            }
#pragma unroll
            for (int mi = 0; mi < 2; mi++)
#pragma unroll
                for (int ni = 0; ni < 4; ni++)
                    mma_f16(acc[mi][ni], a[mi], b[ni], acc[mi][ni]);
        }
    }
}

// ---------------------------------------------------------------------------
// QKV GEMM: q -> fp32 (pre-scaled); k, v -> fp16
// ---------------------------------------------------------------------------
__global__ __launch_bounds__(256) void qkv_gemm_kernel()
{
    __shared__ __align__(1024) char smg[24576];
    const uint32_t sb = smem_u32(smg);
    const int pix0 = blockIdx.x * 128;
    const int n0   = blockIdx.y * 64;
    const int m    = blockIdx.z;

    float acc[2][4][4] = {};
    gemm_core(g_xh, g_w + (size_t)m * CC * CC, pix0, n0, smg, sb, acc);

    const int tid = threadIdx.x, lane = tid & 31, wid = tid >> 5;
    const int wm = wid & 3, wn = wid >> 2;
    const int g = lane >> 2, tig = lane & 3;

    if (m == 0) {
        const float qs = 0.17677669529663687f;
#pragma unroll
        for (int mi = 0; mi < 2; mi++)
#pragma unroll
            for (int ni = 0; ni < 4; ni++) {
                const int mm = pix0 + wm * 32 + mi * 16 + g;
                const int nn = n0 + wn * 32 + ni * 8 + tig * 2;
                float2 v0 = {acc[mi][ni][0] * qs, acc[mi][ni][1] * qs};
                float2 v1 = {acc[mi][ni][2] * qs, acc[mi][ni][3] * qs};
                *(float2*)(g_q + (size_t)mm * CC + nn) = v0;
                *(float2*)(g_q + (size_t)(mm + 8) * CC + nn) = v1;
            }
    } else {
        __half* out = (m == 1) ? g_kh : g_vh;
#pragma unroll
        for (int mi = 0; mi < 2; mi++)
#pragma unroll
            for (int ni = 0; ni < 4; ni++) {
                const int mm = pix0 + wm * 32 + mi * 16 + g;
                const int nn = n0 + wn * 32 + ni * 8 + tig * 2;
                __half2 v0 = {__float2half_rn(acc[mi][ni][0]),
                              __float2half_rn(acc[mi][ni][1])};
                __half2 v1 = {__float2half_rn(acc[mi][ni][2]),
                              __float2half_rn(acc[mi][ni][3])};
                *(__half2*)(out + (size_t)mm * CC + nn) = v0;
                *(__half2*)(out + (size_t)(mm + 8) * CC + nn) = v1;
            }
    }
}

// ---------------------------------------------------------------------------
// Proj GEMM
// ---------------------------------------------------------------------------
__global__ __launch_bounds__(256) void proj_gemm_kernel(
    const float* __restrict__ bp, float* __restrict__ y)
{
    __shared__ __align__(1024) char smg[36864];
    const uint32_t sb = smem_u32(smg);
    const int pix0 = blockIdx.x * 128;
    const int n0   = blockIdx.y * 64;

    float acc[2][4][4] = {};
    gemm_core(g_oh, g_w + (size_t)3 * CC * CC, pix0, n0, smg, sb, acc);

    __syncthreads();
    float (*buf)[136] = (float(*)[136])smg;   // 64 x 136 fp32 = 34816 B

    const int tid = threadIdx.x, lane = tid & 31, wid = tid >> 5;
    const int wm = wid & 3, wn = wid >> 2;
    const int g = lane >> 2, tig = lane & 3;
#pragma unroll
    for (int mi = 0; mi < 2; mi++)
#pragma unroll
        for (int ni = 0; ni < 4; ni++) {
            const int ml = wm * 32 + mi * 16 + g;
            const int nl = wn * 32 + ni * 8 + tig * 2;
            buf[nl][ml]         = acc[mi][ni][0];
            buf[nl + 1][ml]     = acc[mi][ni][1];
            buf[nl][ml + 8]     = acc[mi][ni][2];
            buf[nl + 1][ml + 8] = acc[mi][ni][3];
        }
    __syncthreads();

    const int b = pix0 / HW_;
    const int hw0 = pix0 % HW_;
#pragma unroll
    for (int it = 0; it < 8; it++) {
        const int idx = tid + it * 256;
        const int o = idx >> 5;
        const int hq = (idx & 31) * 4;
        float4 v = *(float4*)&buf[o][hq];
        const float bv = bp[n0 + o];
        v.x += bv; v.y += bv; v.z += bv; v.w += bv;
        *(float4*)(y + (size_t)b * CC * HW_ + (size_t)(n0 + o) * HW_ + hw0 + hq) = v;
    }
}

// ---------------------------------------------------------------------------
// Neighborhood attention: fp16 k/v halos in smem (80B pixel stride)
// ---------------------------------------------------------------------------
extern __shared__ __align__(16) char sm_raw[];

__global__ __launch_bounds__(256) void attn_kernel(const float* __restrict__ rpb)
{
    __half* ks = (__half*)sm_raw;
    __half* vs = ks + ER * ER * KSTR;
    float*  rs = (float*)(vs + ER * ER * KSTR);   // 169 floats

    const int tile = blockIdx.x;
    const int head = blockIdx.y;
    const int b    = blockIdx.z;
    const int i0   = (tile / (WW / TJ)) * TI;
    const int j0   = (tile % (WW / TJ)) * TJ;
    const int tid  = threadIdx.x;

    const int rb = min(max(i0 - 3, 0), HH - KW);
    const int cb = min(max(j0 - 3, 0), WW - KW);

    const __half* kbase = g_kh + (size_t)b * HW_ * CC + head * HD;
    const __half* vbase = g_vh + (size_t)b * HW_ * CC + head * HD;

    for (int t = tid; t < ER * ER * 4; t += 256) {
        const int pix = t >> 2, seg = t & 3;
        const int rr = min(rb + pix / ER, HH - 1);
        const int cc = min(cb + pix % ER, WW - 1);
        const size_t go = (size_t)(rr * WW + cc) * CC + seg * 8;
        *(uint4*)&ks[pix * KSTR + seg * 8] = *(const uint4*)(kbase + go);
        *(uint4*)&vs[pix * KSTR + seg * 8] = *(const uint4*)(vbase + go);
    }
    if (tid < 169) rs[tid] = rpb[head * 169 + tid];
    __syncthreads();

    const int ti = tid >> 4, tj = tid & 15;
    const int i = i0 + ti, j = j0 + tj;
    const int sh = min(max(i - 3, 0), HH - KW);
    const int sw = min(max(j - 3, 0), WW - KW);
    const int dbi = sh - i + 6, dbj = sw - j + 6;
    const int prow = sh - rb, pcol = sw - cb;

    const float* qp = g_q + ((size_t)(b * HW_) + i * WW + j) * CC + head * HD;
    float q[32];
#pragma unroll
    for (int d = 0; d < 8; d++)
        *(float4*)&q[d * 4] = *(const float4*)(qp + d * 4);

    float lg[49];
    float mx = -1e30f;
#pragma unroll
    for (int ki = 0; ki < KW; ki++) {
#pragma unroll
        for (int kj = 0; kj < KW; kj++) {
            const __half* kp = &ks[((prow + ki) * ER + pcol + kj) * KSTR];
            float acc = 0.f;
#pragma unroll
            for (int s = 0; s < 4; s++) {
                uint4 w = *(const uint4*)(kp + s * 8);
                const uint32_t ww[4] = {w.x, w.y, w.z, w.w};
#pragma unroll
                for (int u = 0; u < 4; u++) {
                    float2 kv = __half22float2(*(const __half2*)&ww[u]);
                    acc += q[s * 8 + u * 2] * kv.x + q[s * 8 + u * 2 + 1] * kv.y;
                }
            }
            acc += rs[(dbi + ki) * 13 + (dbj + kj)];
            lg[ki * KW + kj] = acc;
            mx = fmaxf(mx, acc);
        }
    }

    float s = 0.f;
#pragma unroll
    for (int n = 0; n < 49; n++) {
        float e = __expf(lg[n] - mx);
        lg[n] = e;
        s += e;
    }
    const float inv = 1.0f / s;

    float o[32];
#pragma unroll
    for (int d = 0; d < 32; d++) o[d] = 0.f;

#pragma unroll
    for (int ki = 0; ki < KW; ki++) {
#pragma unroll
        for (int kj = 0; kj < KW; kj++) {
            const float w = lg[ki * KW + kj];
            const __half* vp = &vs[((prow + ki) * ER + pcol + kj) * KSTR];
#pragma unroll
            for (int sg = 0; sg < 4; sg++) {
                uint4 wv = *(const uint4*)(vp + sg * 8);
                const uint32_t ww[4] = {wv.x, wv.y, wv.z, wv.w};
#pragma unroll
                for (int u = 0; u < 4; u++) {
                    float2 vv = __half22float2(*(const __half2*)&ww[u]);
                    o[sg * 8 + u * 2]     += w * vv.x;
                    o[sg * 8 + u * 2 + 1] += w * vv.y;
                }
            }
        }
    }

    // Emit fp16 attn-out for the proj GEMM
    __half h[32];
#pragma unroll
    for (int c = 0; c < 32; c++)
        h[c] = __float2half_rn(o[c] * inv);
    const size_t ob = ((size_t)(b * HW_) + i * WW + j) * CC + head * HD;
#pragma unroll
    for (int u = 0; u < 4; u++)
        *(uint4*)(g_oh + ob + u * 8) = *(const uint4*)&h[u * 8];
}

// ---------------------------------------------------------------------------
extern "C" void kernel_launch(void* const* d_in, const int* in_sizes, int n_in,
                              void* d_out, int out_size)
{
    const float* x   = (const float*)d_in[0];
    const float* wq  = (const float*)d_in[1];
    const float* wk  = (const float*)d_in[2];
    const float* wv  = (const float*)d_in[3];
    const float* wp  = (const float*)d_in[4];
    const float* bp  = (const float*)d_in[5];
    const float* rpb = (const float*)d_in[6];
    float* y = (float*)d_out;

    prep_w_kernel<<<256, 256>>>(wq, wk, wv, wp);
    prep_x_kernel<<<dim3(HW_ / 32, CC / 32, BB), 256>>>(x);

    qkv_gemm_kernel<<<dim3(NPIX / 128, CC / 64, 3), 256>>>();

    const int smem_bytes = 2 * ER * ER * KSTR * 2 + 169 * 4;   // ~78 KB
    (void)cudaFuncSetAttribute(attn_kernel,
                               cudaFuncAttributeMaxDynamicSharedMemorySize,
                               smem_bytes);
    attn_kernel<<<dim3((HH / TI) * (WW / TJ), HEADS, BB), 256, smem_bytes>>>(rpb);

    proj_gemm_kernel<<<dim3(NPIX / 128, CC / 64), 256>>>(bp, y);
}

// round 13
// speedup vs baseline: 3.1977x; 1.0555x over previous
#include <cuda_runtime.h>
#include <cuda_fp16.h>
#include <cstdint>

// Problem constants
#define BB    8
#define CC    256
#define HH    96
#define WW    96
#define HEADS 8
#define HD    32
#define KW    7
#define HW_   (HH * WW)          // 9216
#define NPIX  (BB * HW_)         // 73728

// Attention tiling
#define TI   16
#define TJ   16
#define ER   22                  // halo edge
#define KSTR 40                  // smem pixel stride in halfs (80 bytes)

// Scratch
__device__ float  g_q [(size_t)NPIX * CC];
__device__ __half g_kh[(size_t)NPIX * CC];
__device__ __half g_vh[(size_t)NPIX * CC];
__device__ __half g_xh[(size_t)NPIX * CC];
__device__ __half g_oh[(size_t)NPIX * CC];
__device__ __half g_w [4 * CC * CC];

// ---------------------------------------------------------------------------
// Helpers
// ---------------------------------------------------------------------------
__device__ __forceinline__ uint32_t smem_u32(const void* p) {
    uint32_t a;
    asm("{ .reg .u64 t; cvta.to.shared.u64 t, %1; cvt.u32.u64 %0, t; }"
        : "=r"(a) : "l"(p));
    return a;
}

__device__ __forceinline__ void ldsm_x4(uint32_t* r, uint32_t addr) {
    asm volatile("ldmatrix.sync.aligned.m8n8.x4.shared.b16 {%0,%1,%2,%3}, [%4];"
        : "=r"(r[0]), "=r"(r[1]), "=r"(r[2]), "=r"(r[3]) : "r"(addr));
}

__device__ __forceinline__ void mma_f16(float* d, const uint32_t* a,
                                        const uint32_t* b, const float* c) {
    asm volatile(
        "mma.sync.aligned.m16n8k16.row.col.f32.f16.f16.f32 "
        "{%0,%1,%2,%3}, {%4,%5,%6,%7}, {%8,%9}, {%10,%11,%12,%13};"
        : "=f"(d[0]), "=f"(d[1]), "=f"(d[2]), "=f"(d[3])
        : "r"(a[0]), "r"(a[1]), "r"(a[2]), "r"(a[3]),
          "r"(b[0]), "r"(b[1]),
          "f"(c[0]), "f"(c[1]), "f"(c[2]), "f"(c[3]));
}

#define SW128(o) ((o) ^ (((o) >> 3) & 0x70))

// gemm smem: two buffers of (A 16KB + B 8KB)
#define CH_BYTES 24576
#define GB_OFF   16384

// ---------------------------------------------------------------------------
// prep_w: wq/wk/wv/wp fp32 [256,256] -> fp16 [1024,256]
// ---------------------------------------------------------------------------
__global__ __launch_bounds__(256) void prep_w_kernel(
    const float* __restrict__ wq, const float* __restrict__ wk,
    const float* __restrict__ wv, const float* __restrict__ wp)
{
    const int t  = blockIdx.x * 256 + threadIdx.x;
    const int r  = t >> 6;
    const int c4 = (t & 63) * 4;
    const float* w = (r < 256) ? wq : (r < 512) ? wk : (r < 768) ? wv : wp;
    const int lr = r & 255;
    float4 v = *(const float4*)(w + (size_t)lr * CC + c4);
    __half h[4] = {__float2half_rn(v.x), __float2half_rn(v.y),
                   __float2half_rn(v.z), __float2half_rn(v.w)};
    *(uint64_t*)&g_w[(size_t)r * CC + c4] = *(const uint64_t*)h;
}

// ---------------------------------------------------------------------------
// prep_x: x (B,C,HW) fp32 -> g_xh fp16 [pix][C]
// ---------------------------------------------------------------------------
__global__ __launch_bounds__(256) void prep_x_kernel(const float* __restrict__ x)
{
    __shared__ float t[32][33];
    const int b = blockIdx.z, c0 = blockIdx.y * 32, hw0 = blockIdx.x * 32;
    const int tx = threadIdx.x & 31, ty = threadIdx.x >> 5;
    const float* xb = x + ((size_t)b * CC + c0) * HW_ + hw0;
#pragma unroll
    for (int r = 0; r < 4; r++)
        t[ty + r * 8][tx] = xb[(size_t)(ty + r * 8) * HW_ + tx];
    __syncthreads();
#pragma unroll
    for (int r = 0; r < 4; r++) {
        const int hw = ty + r * 8;
        const size_t o = (size_t)(b * HW_ + hw0 + hw) * CC + c0 + tx;
        g_xh[o] = __float2half_rn(t[tx][hw]);
    }
}

// ---------------------------------------------------------------------------
// GEMM core: C[128 pix x 64 n] += A[pix][k] * B[n][k], fp16, K=256.
// Double-buffered smem pipeline: global loads of chunk kc+1 overlap MMA of kc.
// ---------------------------------------------------------------------------
__device__ __forceinline__ void gemm_core(
    const __half* __restrict__ A, const __half* __restrict__ B,
    int pix0, int n0, char* smg, uint32_t sb, float acc[2][4][4])
{
    const int tid  = threadIdx.x;
    const int lane = tid & 31;
    const int wid  = tid >> 5;
    const int wm   = wid & 3;
    const int wn   = wid >> 2;

    const int r8  = lane & 7, sel = lane >> 3;
    const uint32_t a_row = (uint32_t)((sel & 1) * 8 + r8);
    const uint32_t a_kbo = (uint32_t)((sel >> 1) * 16);
    const uint32_t b_row = (uint32_t)((sel >> 1) * 8 + r8);
    const uint32_t b_kbo = (uint32_t)((sel & 1) * 16);

    const int srow_a = tid >> 3, sseg = tid & 7;  // staging coords

    uint4 ra[4], rb[2];

    // global load of chunk kc into registers
    auto g_load = [&](int kc) {
        const int k0 = kc * 64;
#pragma unroll
        for (int i = 0; i < 4; i++) {
            const int row = srow_a + i * 32;
            ra[i] = *(const uint4*)(A + (size_t)(pix0 + row) * CC + k0 + sseg * 8);
        }
#pragma unroll
        for (int i = 0; i < 2; i++) {
            const int row = srow_a + i * 32;
            rb[i] = *(const uint4*)(B + (size_t)(n0 + row) * CC + k0 + sseg * 8);
        }
    };
    // store registers into smem buffer
    auto s_store = [&](int buf) {
        char* base = smg + buf * CH_BYTES;
#pragma unroll
        for (int i = 0; i < 4; i++) {
            const int row = srow_a + i * 32;
            *(uint4*)(base + SW128((uint32_t)(row * 128 + sseg * 16))) = ra[i];
        }
#pragma unroll
        for (int i = 0; i < 2; i++) {
            const int row = srow_a + i * 32;
            *(uint4*)(base + GB_OFF + SW128((uint32_t)(row * 128 + sseg * 16))) = rb[i];
        }
    };

    g_load(0);
    s_store(0);
    __syncthreads();

    for (int kc = 0; kc < 4; kc++) {
        if (kc < 3) g_load(kc + 1);           // in flight during MMA below

        const uint32_t sbuf = sb + (kc & 1) * CH_BYTES;
#pragma unroll
        for (int kk = 0; kk < 4; kk++) {
            uint32_t a[2][4], b[4][2];
#pragma unroll
            for (int mi = 0; mi < 2; mi++) {
                const uint32_t off =
                    (uint32_t)((wm * 32 + mi * 16 + a_row) * 128) + kk * 32 + a_kbo;
                ldsm_x4(a[mi], sbuf + SW128(off));
            }
#pragma unroll
            for (int np = 0; np < 2; np++) {
                const uint32_t off =
                    (uint32_t)((wn * 32 + np * 16 + b_row) * 128) + kk * 32 + b_kbo;
                uint32_t r[4];
                ldsm_x4(r, sbuf + GB_OFF + SW128(off));
                b[np * 2][0] = r[0]; b[np * 2][1] = r[1];
                b[np * 2 + 1][0] = r[2]; b[np * 2 + 1][1] = r[3];
            }
#pragma unroll
            for (int mi = 0; mi < 2; mi++)
#pragma unroll
                for (int ni = 0; ni < 4; ni++)
                    mma_f16(acc[mi][ni], a[mi], b[ni], acc[mi][ni]);
        }

        if (kc < 3) {
            __syncthreads();                   // all warps done with buf (kc-1)&1
            s_store((kc + 1) & 1);
            __syncthreads();                   // chunk kc+1 visible
        }
    }
}

// ---------------------------------------------------------------------------
// QKV GEMM: q -> fp32 (pre-scaled); k, v -> fp16
// ---------------------------------------------------------------------------
__global__ __launch_bounds__(256) void qkv_gemm_kernel()
{
    __shared__ __align__(1024) char smg[2 * CH_BYTES];
    const uint32_t sb = smem_u32(smg);
    const int pix0 = blockIdx.x * 128;
    const int n0   = blockIdx.y * 64;
    const int m    = blockIdx.z;

    float acc[2][4][4] = {};
    gemm_core(g_xh, g_w + (size_t)m * CC * CC, pix0, n0, smg, sb, acc);

    const int tid = threadIdx.x, lane = tid & 31, wid = tid >> 5;
    const int wm = wid & 3, wn = wid >> 2;
    const int g = lane >> 2, tig = lane & 3;

    if (m == 0) {
        const float qs = 0.17677669529663687f;
#pragma unroll
        for (int mi = 0; mi < 2; mi++)
#pragma unroll
            for (int ni = 0; ni < 4; ni++) {
                const int mm = pix0 + wm * 32 + mi * 16 + g;
                const int nn = n0 + wn * 32 + ni * 8 + tig * 2;
                float2 v0 = {acc[mi][ni][0] * qs, acc[mi][ni][1] * qs};
                float2 v1 = {acc[mi][ni][2] * qs, acc[mi][ni][3] * qs};
                *(float2*)(g_q + (size_t)mm * CC + nn) = v0;
                *(float2*)(g_q + (size_t)(mm + 8) * CC + nn) = v1;
            }
    } else {
        __half* out = (m == 1) ? g_kh : g_vh;
#pragma unroll
        for (int mi = 0; mi < 2; mi++)
#pragma unroll
            for (int ni = 0; ni < 4; ni++) {
                const int mm = pix0 + wm * 32 + mi * 16 + g;
                const int nn = n0 + wn * 32 + ni * 8 + tig * 2;
                __half2 v0 = {__float2half_rn(acc[mi][ni][0]),
                              __float2half_rn(acc[mi][ni][1])};
                __half2 v1 = {__float2half_rn(acc[mi][ni][2]),
                              __float2half_rn(acc[mi][ni][3])};
                *(__half2*)(out + (size_t)mm * CC + nn) = v0;
                *(__half2*)(out + (size_t)(mm + 8) * CC + nn) = v1;
            }
    }
}

// ---------------------------------------------------------------------------
// Proj GEMM
// ---------------------------------------------------------------------------
__global__ __launch_bounds__(256) void proj_gemm_kernel(
    const float* __restrict__ bp, float* __restrict__ y)
{
    __shared__ __align__(1024) char smg[2 * CH_BYTES];
    const uint32_t sb = smem_u32(smg);
    const int pix0 = blockIdx.x * 128;
    const int n0   = blockIdx.y * 64;

    float acc[2][4][4] = {};
    gemm_core(g_oh, g_w + (size_t)3 * CC * CC, pix0, n0, smg, sb, acc);

    __syncthreads();
    float (*buf)[136] = (float(*)[136])smg;   // 64 x 136 fp32 = 34816 B

    const int tid = threadIdx.x, lane = tid & 31, wid = tid >> 5;
    const int wm = wid & 3, wn = wid >> 2;
    const int g = lane >> 2, tig = lane & 3;
#pragma unroll
    for (int mi = 0; mi < 2; mi++)
#pragma unroll
        for (int ni = 0; ni < 4; ni++) {
            const int ml = wm * 32 + mi * 16 + g;
            const int nl = wn * 32 + ni * 8 + tig * 2;
            buf[nl][ml]         = acc[mi][ni][0];
            buf[nl + 1][ml]     = acc[mi][ni][1];
            buf[nl][ml + 8]     = acc[mi][ni][2];
            buf[nl + 1][ml + 8] = acc[mi][ni][3];
        }
    __syncthreads();

    const int b = pix0 / HW_;
    const int hw0 = pix0 % HW_;
#pragma unroll
    for (int it = 0; it < 8; it++) {
        const int idx = tid + it * 256;
        const int o = idx >> 5;
        const int hq = (idx & 31) * 4;
        float4 v = *(float4*)&buf[o][hq];
        const float bv = bp[n0 + o];
        v.x += bv; v.y += bv; v.z += bv; v.w += bv;
        *(float4*)(y + (size_t)b * CC * HW_ + (size_t)(n0 + o) * HW_ + hw0 + hq) = v;
    }
}

// ---------------------------------------------------------------------------
// Neighborhood attention: fp16 k/v halos; 8-way split qk accumulators
// ---------------------------------------------------------------------------
extern __shared__ __align__(16) char sm_raw[];

__global__ __launch_bounds__(256) void attn_kernel(const float* __restrict__ rpb)
{
    __half* ks = (__half*)sm_raw;
    __half* vs = ks + ER * ER * KSTR;
    float*  rs = (float*)(vs + ER * ER * KSTR);   // 169 floats

    const int tile = blockIdx.x;
    const int head = blockIdx.y;
    const int b    = blockIdx.z;
    const int i0   = (tile / (WW / TJ)) * TI;
    const int j0   = (tile % (WW / TJ)) * TJ;
    const int tid  = threadIdx.x;

    const int rb = min(max(i0 - 3, 0), HH - KW);
    const int cb = min(max(j0 - 3, 0), WW - KW);

    const __half* kbase = g_kh + (size_t)b * HW_ * CC + head * HD;
    const __half* vbase = g_vh + (size_t)b * HW_ * CC + head * HD;

    for (int t = tid; t < ER * ER * 4; t += 256) {
        const int pix = t >> 2, seg = t & 3;
        const int rr = min(rb + pix / ER, HH - 1);
        const int cc = min(cb + pix % ER, WW - 1);
        const size_t go = (size_t)(rr * WW + cc) * CC + seg * 8;
        *(uint4*)&ks[pix * KSTR + seg * 8] = *(const uint4*)(kbase + go);
        *(uint4*)&vs[pix * KSTR + seg * 8] = *(const uint4*)(vbase + go);
    }
    if (tid < 169) rs[tid] = rpb[head * 169 + tid];
    __syncthreads();

    const int ti = tid >> 4, tj = tid & 15;
    const int i = i0 + ti, j = j0 + tj;
    const int sh = min(max(i - 3, 0), HH - KW);
    const int sw = min(max(j - 3, 0), WW - KW);
    const int dbi = sh - i + 6, dbj = sw - j + 6;
    const int prow = sh - rb, pcol = sw - cb;

    const float* qp = g_q + ((size_t)(b * HW_) + i * WW + j) * CC + head * HD;
    float q[32];
#pragma unroll
    for (int d = 0; d < 8; d++)
        *(float4*)&q[d * 4] = *(const float4*)(qp + d * 4);

    float lg[49];
    float mx = -1e30f;
#pragma unroll
    for (int ki = 0; ki < KW; ki++) {
#pragma unroll
        for (int kj = 0; kj < KW; kj++) {
            const __half* kp = &ks[((prow + ki) * ER + pcol + kj) * KSTR];
            // 8 independent accumulators -> dependency chains of length 4
            float pa[8];
#pragma unroll
            for (int u = 0; u < 8; u++) pa[u] = 0.f;
#pragma unroll
            for (int s = 0; s < 4; s++) {
                uint4 w = *(const uint4*)(kp + s * 8);
                const uint32_t ww[4] = {w.x, w.y, w.z, w.w};
#pragma unroll
                for (int u = 0; u < 4; u++) {
                    float2 kv = __half22float2(*(const __half2*)&ww[u]);
                    const int ai = s * 2 + (u >> 1);   // 0..7
                    pa[ai] += q[s * 8 + u * 2] * kv.x;
                    pa[ai] += q[s * 8 + u * 2 + 1] * kv.y;
                }
            }
            float accv = ((pa[0] + pa[1]) + (pa[2] + pa[3])) +
                         ((pa[4] + pa[5]) + (pa[6] + pa[7]));
            accv += rs[(dbi + ki) * 13 + (dbj + kj)];
            lg[ki * KW + kj] = accv;
            mx = fmaxf(mx, accv);
        }
    }

    // 4-way split softmax sum
    float s0 = 0.f, s1 = 0.f, s2 = 0.f, s3 = 0.f;
#pragma unroll
    for (int n = 0; n < 48; n += 4) {
        float e0 = __expf(lg[n] - mx);
        float e1 = __expf(lg[n + 1] - mx);
        float e2 = __expf(lg[n + 2] - mx);
        float e3 = __expf(lg[n + 3] - mx);
        lg[n] = e0; lg[n + 1] = e1; lg[n + 2] = e2; lg[n + 3] = e3;
        s0 += e0; s1 += e1; s2 += e2; s3 += e3;
    }
    {
        float e = __expf(lg[48] - mx);
        lg[48] = e;
        s0 += e;
    }
    const float inv = 1.0f / ((s0 + s1) + (s2 + s3));

    float o[32];
#pragma unroll
    for (int d = 0; d < 32; d++) o[d] = 0.f;

#pragma unroll
    for (int ki = 0; ki < KW; ki++) {
#pragma unroll
        for (int kj = 0; kj < KW; kj++) {
            const float w = lg[ki * KW + kj];
            const __half* vp = &vs[((prow + ki) * ER + pcol + kj) * KSTR];
#pragma unroll
            for (int sg = 0; sg < 4; sg++) {
                uint4 wv = *(const uint4*)(vp + sg * 8);
                const uint32_t ww[4] = {wv.x, wv.y, wv.z, wv.w};
#pragma unroll
                for (int u = 0; u < 4; u++) {
                    float2 vv = __half22float2(*(const __half2*)&ww[u]);
                    o[sg * 8 + u * 2]     += w * vv.x;
                    o[sg * 8 + u * 2 + 1] += w * vv.y;
                }
            }
        }
    }

    // Emit fp16 attn-out for the proj GEMM
    __half h[32];
#pragma unroll
    for (int c = 0; c < 32; c++)
        h[c] = __float2half_rn(o[c] * inv);
    const size_t ob = ((size_t)(b * HW_) + i * WW + j) * CC + head * HD;
#pragma unroll
    for (int u = 0; u < 4; u++)
        *(uint4*)(g_oh + ob + u * 8) = *(const uint4*)&h[u * 8];
}

// ---------------------------------------------------------------------------
extern "C" void kernel_launch(void* const* d_in, const int* in_sizes, int n_in,
                              void* d_out, int out_size)
{
    const float* x   = (const float*)d_in[0];
    const float* wq  = (const float*)d_in[1];
    const float* wk  = (const float*)d_in[2];
    const float* wv  = (const float*)d_in[3];
    const float* wp  = (const float*)d_in[4];
    const float* bp  = (const float*)d_in[5];
    const float* rpb = (const float*)d_in[6];
    float* y = (float*)d_out;

    prep_w_kernel<<<256, 256>>>(wq, wk, wv, wp);
    prep_x_kernel<<<dim3(HW_ / 32, CC / 32, BB), 256>>>(x);

    qkv_gemm_kernel<<<dim3(NPIX / 128, CC / 64, 3), 256>>>();

    const int smem_bytes = 2 * ER * ER * KSTR * 2 + 169 * 4;   // ~78 KB
    (void)cudaFuncSetAttribute(attn_kernel,
                               cudaFuncAttributeMaxDynamicSharedMemorySize,
                               smem_bytes);
    attn_kernel<<<dim3((HH / TI) * (WW / TJ), HEADS, BB), 256, smem_bytes>>>(rpb);

    proj_gemm_kernel<<<dim3(NPIX / 128, CC / 64), 256>>>(bp, y);
}

// round 14
// speedup vs baseline: 3.6853x; 1.1525x over previous
#include <cuda_runtime.h>
#include <cuda_fp16.h>
#include <cstdint>

// Problem constants
#define BB    8
#define CC    256
#define HH    96
#define WW    96
#define HEADS 8
#define HD    32
#define KW    7
#define HW_   (HH * WW)          // 9216
#define NPIX  (BB * HW_)         // 73728

// Attention tiling
#define TI   16
#define TJ   16
#define ER   22                  // halo edge
#define KSTR 40                  // smem pixel stride in halfs (80 bytes)

// Scratch
__device__ __half g_qh[(size_t)NPIX * CC];
__device__ __half g_kh[(size_t)NPIX * CC];
__device__ __half g_vh[(size_t)NPIX * CC];
__device__ __half g_xh[(size_t)NPIX * CC];
__device__ __half g_oh[(size_t)NPIX * CC];
__device__ __half g_w [4 * CC * CC];

// ---------------------------------------------------------------------------
// Helpers
// ---------------------------------------------------------------------------
__device__ __forceinline__ uint32_t smem_u32(const void* p) {
    uint32_t a;
    asm("{ .reg .u64 t; cvta.to.shared.u64 t, %1; cvt.u32.u64 %0, t; }"
        : "=r"(a) : "l"(p));
    return a;
}

__device__ __forceinline__ void ldsm_x4(uint32_t* r, uint32_t addr) {
    asm volatile("ldmatrix.sync.aligned.m8n8.x4.shared.b16 {%0,%1,%2,%3}, [%4];"
        : "=r"(r[0]), "=r"(r[1]), "=r"(r[2]), "=r"(r[3]) : "r"(addr));
}

__device__ __forceinline__ void mma_f16(float* d, const uint32_t* a,
                                        const uint32_t* b, const float* c) {
    asm volatile(
        "mma.sync.aligned.m16n8k16.row.col.f32.f16.f16.f32 "
        "{%0,%1,%2,%3}, {%4,%5,%6,%7}, {%8,%9}, {%10,%11,%12,%13};"
        : "=f"(d[0]), "=f"(d[1]), "=f"(d[2]), "=f"(d[3])
        : "r"(a[0]), "r"(a[1]), "r"(a[2]), "r"(a[3]),
          "r"(b[0]), "r"(b[1]),
          "f"(c[0]), "f"(c[1]), "f"(c[2]), "f"(c[3]));
}

#define SW128(o) ((o) ^ (((o) >> 3) & 0x70))

// gemm smem: two buffers of (A 16KB + B 8KB)
#define CH_BYTES 24576
#define GB_OFF   16384

// ---------------------------------------------------------------------------
// prep_w: wq/wk/wv/wp fp32 [256,256] -> fp16 [1024,256]
// ---------------------------------------------------------------------------
__global__ __launch_bounds__(256) void prep_w_kernel(
    const float* __restrict__ wq, const float* __restrict__ wk,
    const float* __restrict__ wv, const float* __restrict__ wp)
{
    const int t  = blockIdx.x * 256 + threadIdx.x;
    const int r  = t >> 6;
    const int c4 = (t & 63) * 4;
    const float* w = (r < 256) ? wq : (r < 512) ? wk : (r < 768) ? wv : wp;
    const int lr = r & 255;
    float4 v = *(const float4*)(w + (size_t)lr * CC + c4);
    __half h[4] = {__float2half_rn(v.x), __float2half_rn(v.y),
                   __float2half_rn(v.z), __float2half_rn(v.w)};
    *(uint64_t*)&g_w[(size_t)r * CC + c4] = *(const uint64_t*)h;
}

// ---------------------------------------------------------------------------
// prep_x: x (B,C,HW) fp32 -> g_xh fp16 [pix][C]
// ---------------------------------------------------------------------------
__global__ __launch_bounds__(256) void prep_x_kernel(const float* __restrict__ x)
{
    __shared__ float t[32][33];
    const int b = blockIdx.z, c0 = blockIdx.y * 32, hw0 = blockIdx.x * 32;
    const int tx = threadIdx.x & 31, ty = threadIdx.x >> 5;
    const float* xb = x + ((size_t)b * CC + c0) * HW_ + hw0;
#pragma unroll
    for (int r = 0; r < 4; r++)
        t[ty + r * 8][tx] = xb[(size_t)(ty + r * 8) * HW_ + tx];
    __syncthreads();
#pragma unroll
    for (int r = 0; r < 4; r++) {
        const int hw = ty + r * 8;
        const size_t o = (size_t)(b * HW_ + hw0 + hw) * CC + c0 + tx;
        g_xh[o] = __float2half_rn(t[tx][hw]);
    }
}

// ---------------------------------------------------------------------------
// GEMM core: C[128 pix x 64 n] += A[pix][k] * B[n][k], fp16, K=256.
// Double-buffered smem pipeline.
// ---------------------------------------------------------------------------
__device__ __forceinline__ void gemm_core(
    const __half* __restrict__ A, const __half* __restrict__ B,
    int pix0, int n0, char* smg, uint32_t sb, float acc[2][4][4])
{
    const int tid  = threadIdx.x;
    const int lane = tid & 31;
    const int wid  = tid >> 5;
    const int wm   = wid & 3;
    const int wn   = wid >> 2;

    const int r8  = lane & 7, sel = lane >> 3;
    const uint32_t a_row = (uint32_t)((sel & 1) * 8 + r8);
    const uint32_t a_kbo = (uint32_t)((sel >> 1) * 16);
    const uint32_t b_row = (uint32_t)((sel >> 1) * 8 + r8);
    const uint32_t b_kbo = (uint32_t)((sel & 1) * 16);

    const int srow_a = tid >> 3, sseg = tid & 7;

    uint4 ra[4], rb[2];

    auto g_load = [&](int kc) {
        const int k0 = kc * 64;
#pragma unroll
        for (int i = 0; i < 4; i++) {
            const int row = srow_a + i * 32;
            ra[i] = *(const uint4*)(A + (size_t)(pix0 + row) * CC + k0 + sseg * 8);
        }
#pragma unroll
        for (int i = 0; i < 2; i++) {
            const int row = srow_a + i * 32;
            rb[i] = *(const uint4*)(B + (size_t)(n0 + row) * CC + k0 + sseg * 8);
        }
    };
    auto s_store = [&](int buf) {
        char* base = smg + buf * CH_BYTES;
#pragma unroll
        for (int i = 0; i < 4; i++) {
            const int row = srow_a + i * 32;
            *(uint4*)(base + SW128((uint32_t)(row * 128 + sseg * 16))) = ra[i];
        }
#pragma unroll
        for (int i = 0; i < 2; i++) {
            const int row = srow_a + i * 32;
            *(uint4*)(base + GB_OFF + SW128((uint32_t)(row * 128 + sseg * 16))) = rb[i];
        }
    };

    g_load(0);
    s_store(0);
    __syncthreads();

    for (int kc = 0; kc < 4; kc++) {
        if (kc < 3) g_load(kc + 1);

        const uint32_t sbuf = sb + (kc & 1) * CH_BYTES;
#pragma unroll
        for (int kk = 0; kk < 4; kk++) {
            uint32_t a[2][4], b[4][2];
#pragma unroll
            for (int mi = 0; mi < 2; mi++) {
                const uint32_t off =
                    (uint32_t)((wm * 32 + mi * 16 + a_row) * 128) + kk * 32 + a_kbo;
                ldsm_x4(a[mi], sbuf + SW128(off));
            }
#pragma unroll
            for (int np = 0; np < 2; np++) {
                const uint32_t off =
                    (uint32_t)((wn * 32 + np * 16 + b_row) * 128) + kk * 32 + b_kbo;
                uint32_t r[4];
                ldsm_x4(r, sbuf + GB_OFF + SW128(off));
                b[np * 2][0] = r[0]; b[np * 2][1] = r[1];
                b[np * 2 + 1][0] = r[2]; b[np * 2 + 1][1] = r[3];
            }
#pragma unroll
            for (int mi = 0; mi < 2; mi++)
#pragma unroll
                for (int ni = 0; ni < 4; ni++)
                    mma_f16(acc[mi][ni], a[mi], b[ni], acc[mi][ni]);
        }

        if (kc < 3) {
            __syncthreads();
            s_store((kc + 1) & 1);
            __syncthreads();
        }
    }
}

// ---------------------------------------------------------------------------
// QKV GEMM: q (pre-scaled), k, v all -> fp16
// ---------------------------------------------------------------------------
__global__ __launch_bounds__(256) void qkv_gemm_kernel()
{
    __shared__ __align__(1024) char smg[2 * CH_BYTES];
    const uint32_t sb = smem_u32(smg);
    const int pix0 = blockIdx.x * 128;
    const int n0   = blockIdx.y * 64;
    const int m    = blockIdx.z;

    float acc[2][4][4] = {};
    gemm_core(g_xh, g_w + (size_t)m * CC * CC, pix0, n0, smg, sb, acc);

    const int tid = threadIdx.x, lane = tid & 31, wid = tid >> 5;
    const int wm = wid & 3, wn = wid >> 2;
    const int g = lane >> 2, tig = lane & 3;

    __half* out = (m == 0) ? g_qh : (m == 1) ? g_kh : g_vh;
    const float qs = (m == 0) ? 0.17677669529663687f : 1.0f;
#pragma unroll
    for (int mi = 0; mi < 2; mi++)
#pragma unroll
        for (int ni = 0; ni < 4; ni++) {
            const int mm = pix0 + wm * 32 + mi * 16 + g;
            const int nn = n0 + wn * 32 + ni * 8 + tig * 2;
            __half2 v0 = {__float2half_rn(acc[mi][ni][0] * qs),
                          __float2half_rn(acc[mi][ni][1] * qs)};
            __half2 v1 = {__float2half_rn(acc[mi][ni][2] * qs),
                          __float2half_rn(acc[mi][ni][3] * qs)};
            *(__half2*)(out + (size_t)mm * CC + nn) = v0;
            *(__half2*)(out + (size_t)(mm + 8) * CC + nn) = v1;
        }
}

// ---------------------------------------------------------------------------
// Proj GEMM
// ---------------------------------------------------------------------------
__global__ __launch_bounds__(256) void proj_gemm_kernel(
    const float* __restrict__ bp, float* __restrict__ y)
{
    __shared__ __align__(1024) char smg[2 * CH_BYTES];
    const uint32_t sb = smem_u32(smg);
    const int pix0 = blockIdx.x * 128;
    const int n0   = blockIdx.y * 64;

    float acc[2][4][4] = {};
    gemm_core(g_oh, g_w + (size_t)3 * CC * CC, pix0, n0, smg, sb, acc);

    __syncthreads();
    float (*buf)[136] = (float(*)[136])smg;

    const int tid = threadIdx.x, lane = tid & 31, wid = tid >> 5;
    const int wm = wid & 3, wn = wid >> 2;
    const int g = lane >> 2, tig = lane & 3;
#pragma unroll
    for (int mi = 0; mi < 2; mi++)
#pragma unroll
        for (int ni = 0; ni < 4; ni++) {
            const int ml = wm * 32 + mi * 16 + g;
            const int nl = wn * 32 + ni * 8 + tig * 2;
            buf[nl][ml]         = acc[mi][ni][0];
            buf[nl + 1][ml]     = acc[mi][ni][1];
            buf[nl][ml + 8]     = acc[mi][ni][2];
            buf[nl + 1][ml + 8] = acc[mi][ni][3];
        }
    __syncthreads();

    const int b = pix0 / HW_;
    const int hw0 = pix0 % HW_;
#pragma unroll
    for (int it = 0; it < 8; it++) {
        const int idx = tid + it * 256;
        const int o = idx >> 5;
        const int hq = (idx & 31) * 4;
        float4 v = *(float4*)&buf[o][hq];
        const float bv = bp[n0 + o];
        v.x += bv; v.y += bv; v.z += bv; v.w += bv;
        *(float4*)(y + (size_t)b * CC * HW_ + (size_t)(n0 + o) * HW_ + hw0 + hq) = v;
    }
}

// ---------------------------------------------------------------------------
// Neighborhood attention: fp16 halos, HFMA2 math with short-chain fp32 flush
// ---------------------------------------------------------------------------
extern __shared__ __align__(16) char sm_raw[];

__global__ __launch_bounds__(256) void attn_kernel(const float* __restrict__ rpb)
{
    __half* ks = (__half*)sm_raw;
    __half* vs = ks + ER * ER * KSTR;
    float*  rs = (float*)(vs + ER * ER * KSTR);   // 169 floats

    const int tile = blockIdx.x;
    const int head = blockIdx.y;
    const int b    = blockIdx.z;
    const int i0   = (tile / (WW / TJ)) * TI;
    const int j0   = (tile % (WW / TJ)) * TJ;
    const int tid  = threadIdx.x;

    const int rb = min(max(i0 - 3, 0), HH - KW);
    const int cb = min(max(j0 - 3, 0), WW - KW);

    const __half* kbase = g_kh + (size_t)b * HW_ * CC + head * HD;
    const __half* vbase = g_vh + (size_t)b * HW_ * CC + head * HD;

    for (int t = tid; t < ER * ER * 4; t += 256) {
        const int pix = t >> 2, seg = t & 3;
        const int rr = min(rb + pix / ER, HH - 1);
        const int cc = min(cb + pix % ER, WW - 1);
        const size_t go = (size_t)(rr * WW + cc) * CC + seg * 8;
        *(uint4*)&ks[pix * KSTR + seg * 8] = *(const uint4*)(kbase + go);
        *(uint4*)&vs[pix * KSTR + seg * 8] = *(const uint4*)(vbase + go);
    }
    if (tid < 169) rs[tid] = rpb[head * 169 + tid];
    __syncthreads();

    const int ti = tid >> 4, tj = tid & 15;
    const int i = i0 + ti, j = j0 + tj;
    const int sh = min(max(i - 3, 0), HH - KW);
    const int sw = min(max(j - 3, 0), WW - KW);
    const int dbi = sh - i + 6, dbj = sw - j + 6;
    const int prow = sh - rb, pcol = sw - cb;

    // q: 32 fp16 = 16 half2 in registers
    const __half* qp = g_qh + ((size_t)(b * HW_) + i * WW + j) * CC + head * HD;
    uint32_t qr[16];
#pragma unroll
    for (int u = 0; u < 4; u++)
        *(uint4*)&qr[u * 4] = *(const uint4*)(qp + u * 8);

    const __half2 hz = __float2half2_rn(0.0f);

    float lg[49];
    float mx = -1e30f;
#pragma unroll
    for (int ki = 0; ki < KW; ki++) {
#pragma unroll
        for (int kj = 0; kj < KW; kj++) {
            const __half* kp = &ks[((prow + ki) * ER + pcol + kj) * KSTR];
            __half2 pa[4] = {hz, hz, hz, hz};   // 4-deep fp16 chains
#pragma unroll
            for (int s = 0; s < 4; s++) {
                uint4 w = *(const uint4*)(kp + s * 8);
                const uint32_t ww[4] = {w.x, w.y, w.z, w.w};
#pragma unroll
                for (int u = 0; u < 4; u++)
                    pa[s] = __hfma2(*(const __half2*)&qr[s * 4 + u],
                                    *(const __half2*)&ww[u], pa[s]);
            }
            float2 f0 = __half22float2(pa[0]);
            float2 f1 = __half22float2(pa[1]);
            float2 f2 = __half22float2(pa[2]);
            float2 f3 = __half22float2(pa[3]);
            float accv = ((f0.x + f0.y) + (f1.x + f1.y)) +
                         ((f2.x + f2.y) + (f3.x + f3.y));
            accv += rs[(dbi + ki) * 13 + (dbj + kj)];
            lg[ki * KW + kj] = accv;
            mx = fmaxf(mx, accv);
        }
    }

    float s0 = 0.f, s1 = 0.f, s2 = 0.f, s3 = 0.f;
#pragma unroll
    for (int n = 0; n < 48; n += 4) {
        float e0 = __expf(lg[n] - mx);
        float e1 = __expf(lg[n + 1] - mx);
        float e2 = __expf(lg[n + 2] - mx);
        float e3 = __expf(lg[n + 3] - mx);
        lg[n] = e0; lg[n + 1] = e1; lg[n + 2] = e2; lg[n + 3] = e3;
        s0 += e0; s1 += e1; s2 += e2; s3 += e3;
    }
    {
        float e = __expf(lg[48] - mx);
        lg[48] = e;
        s0 += e;
    }
    const float inv = 1.0f / ((s0 + s1) + (s2 + s3));

    float o[32];
#pragma unroll
    for (int d = 0; d < 32; d++) o[d] = 0.f;

#pragma unroll
    for (int ki = 0; ki < KW; ki++) {
        // fp16 row accumulators, flushed to fp32 after 7 taps
        __half2 oh[16];
#pragma unroll
        for (int u = 0; u < 16; u++) oh[u] = hz;
#pragma unroll
        for (int kj = 0; kj < KW; kj++) {
            const __half2 wh = __float2half2_rn(lg[ki * KW + kj]);
            const __half* vp = &vs[((prow + ki) * ER + pcol + kj) * KSTR];
#pragma unroll
            for (int sg = 0; sg < 4; sg++) {
                uint4 wv = *(const uint4*)(vp + sg * 8);
                const uint32_t ww[4] = {wv.x, wv.y, wv.z, wv.w};
#pragma unroll
                for (int u = 0; u < 4; u++)
                    oh[sg * 4 + u] = __hfma2(wh, *(const __half2*)&ww[u],
                                             oh[sg * 4 + u]);
            }
        }
#pragma unroll
        for (int u = 0; u < 16; u++) {
            float2 f = __half22float2(oh[u]);
            o[u * 2]     += f.x;
            o[u * 2 + 1] += f.y;
        }
    }

    // Emit fp16 attn-out for the proj GEMM
    __half h[32];
#pragma unroll
    for (int c = 0; c < 32; c++)
        h[c] = __float2half_rn(o[c] * inv);
    const size_t ob = ((size_t)(b * HW_) + i * WW + j) * CC + head * HD;
#pragma unroll
    for (int u = 0; u < 4; u++)
        *(uint4*)(g_oh + ob + u * 8) = *(const uint4*)&h[u * 8];
}

// ---------------------------------------------------------------------------
extern "C" void kernel_launch(void* const* d_in, const int* in_sizes, int n_in,
                              void* d_out, int out_size)
{
    const float* x   = (const float*)d_in[0];
    const float* wq  = (const float*)d_in[1];
    const float* wk  = (const float*)d_in[2];
    const float* wv  = (const float*)d_in[3];
    const float* wp  = (const float*)d_in[4];
    const float* bp  = (const float*)d_in[5];
    const float* rpb = (const float*)d_in[6];
    float* y = (float*)d_out;

    prep_w_kernel<<<256, 256>>>(wq, wk, wv, wp);
    prep_x_kernel<<<dim3(HW_ / 32, CC / 32, BB), 256>>>(x);

    qkv_gemm_kernel<<<dim3(NPIX / 128, CC / 64, 3), 256>>>();

    const int smem_bytes = 2 * ER * ER * KSTR * 2 + 169 * 4;   // ~78 KB
    (void)cudaFuncSetAttribute(attn_kernel,
                               cudaFuncAttributeMaxDynamicSharedMemorySize,
                               smem_bytes);
    attn_kernel<<<dim3((HH / TI) * (WW / TJ), HEADS, BB), 256, smem_bytes>>>(rpb);

    proj_gemm_kernel<<<dim3(NPIX / 128, CC / 64), 256>>>(bp, y);
}